// round 5
// baseline (speedup 1.0000x reference)
#include <cuda_runtime.h>
#include <math.h>
#include <stdint.h>

#define BB 4
#define SS 1024
#define DD 1024
#define HH 16
#define DK 64
#define DFF 4096

// ---------------- scratch (device globals; no allocations allowed) ----------
__device__ float g_xq[BB * SS * DD];      // rounded x_q; reused as mha_out
__device__ float g_xk[BB * SS * DD];      // rounded x_k; reused as sub1_rounded
__device__ float g_xv[BB * SS * DD];      // rounded x_v; reused as ffn2 out
__device__ float g_w0r[DD * DD];
__device__ float g_ff1r[DD * DFF];
__device__ float g_ff2r[DFF * DD];
__device__ float g_wq[DD * DD];
__device__ float g_wk[DD * DD];
__device__ float g_wv[DD * DD];
__device__ float g_q[BB * SS * DD];       // q [B,S,H,DK]
__device__ float g_k[BB * SS * DD];       // k; reused as sub1 (exact)
__device__ float g_v[BB * SS * DD];       // v
__device__ float g_att_raw[(long long)BB * SS * SS]; // last-head raw scores (16MB)
__device__ float g_concat[BB * SS * DD];  // flash O output
__device__ float g_ffn1[(long long)BB * SS * DFF];

// ---------------- helpers ----------------------------------------------------
__device__ __forceinline__ void cp16(float* smem_dst, const float* gmem_src) {
    uint32_t s = (uint32_t)__cvta_generic_to_shared(smem_dst);
    asm volatile("cp.async.ca.shared.global [%0], [%1], 16;" :: "r"(s), "l"(gmem_src));
}
__device__ __forceinline__ void cp_commit() {
    asm volatile("cp.async.commit_group;");
}
template <int N>
__device__ __forceinline__ void cp_wait() {
    asm volatile("cp.async.wait_group %0;" :: "n"(N));
}
__device__ __forceinline__ float rna(float x) {
    uint32_t u;
    asm("cvt.rna.tf32.f32 %0, %1;" : "=r"(u) : "f"(x));
    return __uint_as_float(u);
}
__device__ __forceinline__ void mma8(float* d, const uint32_t* a, const uint32_t* b) {
    asm volatile(
        "mma.sync.aligned.m16n8k8.row.col.f32.tf32.tf32.f32 "
        "{%0,%1,%2,%3}, {%4,%5,%6,%7}, {%8,%9}, {%0,%1,%2,%3};"
        : "+f"(d[0]), "+f"(d[1]), "+f"(d[2]), "+f"(d[3])
        : "r"(a[0]), "r"(a[1]), "r"(a[2]), "r"(a[3]), "r"(b[0]), "r"(b[1]));
}

// ---------------- prep: round-to-nearest tf32 copies -------------------------
__global__ void round_copy(const float* __restrict__ src, float* __restrict__ dst) {
    int i = blockIdx.x * 256 + threadIdx.x;
    float4 v = ((const float4*)src)[i];
    v.x = rna(v.x); v.y = rna(v.y); v.z = rna(v.z); v.w = rna(v.w);
    ((float4*)dst)[i] = v;
}

// repack per-head weights [H,D,DK] -> [D, H*DK], rounded
__global__ void repack_kernel(const float* __restrict__ wq,
                              const float* __restrict__ wk,
                              const float* __restrict__ wv) {
    int idx = blockIdx.x * 256 + threadIdx.x;     // over D*D
    int d = idx >> 10;
    int c = idx & 1023;                            // c = h*DK + k
    int src = ((c >> 6) << 16) | (d << 6) | (c & 63);
    g_wq[idx] = rna(wq[src]);
    g_wk[idx] = rna(wk[src]);
    g_wv[idx] = rna(wv[src]);
}

// ---------------- TF32 GEMM: 128 threads, 4 warps (2x2), warp tile 64x64 ----
// 3-stage cp.async ring. MT=4, NT=8 -> 128 acc regs, 128 B SMEM per MMA.
template <int RELU, int RND>
__global__ __launch_bounds__(128, 2) void gemm_tc3(
    const float* __restrict__ A, const float* __restrict__ Bm,
    const float* __restrict__ bias, float* __restrict__ C,
    int K, int lda, int ldb, int ldc) {
    constexpr int BM = 128, BN = 128, BK = 32;
    constexpr int AST = BK + 4;   // 36
    constexpr int BST = BN + 8;   // 136
    constexpr int STG = BM * AST + BK * BST;   // floats per stage (8960)

    extern __shared__ float sm[];              // [3][STG]

    const int tid = threadIdx.x;
    const int lane = tid & 31, warp = tid >> 5;
    const int wrow = warp >> 1, wcol = warp & 1;
    const int row0 = blockIdx.y * BM, col0 = blockIdx.x * BN;
    const int nk = K / BK;

    auto issue = [&](int kt) {
        float* as = sm + (kt % 3) * STG;
        float* bs = as + BM * AST;
        #pragma unroll
        for (int i = 0; i < 8; i++) {
            int idx = tid + 128 * i;
            int m = idx >> 3, c4 = (idx & 7) * 4;
            cp16(as + m * AST + c4, A + (long long)(row0 + m) * lda + kt * BK + c4);
        }
        #pragma unroll
        for (int i = 0; i < 8; i++) {
            int idx = tid + 128 * i;
            int kk = idx >> 5, c4 = (idx & 31) * 4;
            cp16(bs + kk * BST + c4, Bm + (long long)(kt * BK + kk) * ldb + col0 + c4);
        }
        cp_commit();
    };

    float acc[4][8][4] = {};

    issue(0);
    if (nk > 1) issue(1);

    const int r = lane >> 2, c = lane & 3;
    for (int kt = 0; kt < nk; kt++) {
        if (kt == nk - 1) cp_wait<0>(); else cp_wait<1>();
        __syncthreads();
        if (kt + 2 < nk) issue(kt + 2);

        const float* as = sm + (kt % 3) * STG;
        const float* bs = as + BM * AST;
        #pragma unroll
        for (int ks = 0; ks < 4; ks++) {
            const int k0 = ks * 8;
            uint32_t af[4][4], bf[8][2];
            #pragma unroll
            for (int mt = 0; mt < 4; mt++) {
                int m = wrow * 64 + mt * 16 + r;
                af[mt][0] = *(const uint32_t*)&as[m * AST + k0 + c];
                af[mt][1] = *(const uint32_t*)&as[(m + 8) * AST + k0 + c];
                af[mt][2] = *(const uint32_t*)&as[m * AST + k0 + c + 4];
                af[mt][3] = *(const uint32_t*)&as[(m + 8) * AST + k0 + c + 4];
            }
            #pragma unroll
            for (int nt = 0; nt < 8; nt++) {
                int n = wcol * 64 + nt * 8 + r;
                bf[nt][0] = *(const uint32_t*)&bs[(k0 + c) * BST + n];
                bf[nt][1] = *(const uint32_t*)&bs[(k0 + c + 4) * BST + n];
            }
            #pragma unroll
            for (int mt = 0; mt < 4; mt++)
                #pragma unroll
                for (int nt = 0; nt < 8; nt++)
                    mma8(acc[mt][nt], af[mt], bf[nt]);
        }
        __syncthreads();
    }

    const int c2 = (lane & 3) * 2;
    #pragma unroll
    for (int mt = 0; mt < 4; mt++) {
        int mrow = row0 + wrow * 64 + mt * 16 + r;
        #pragma unroll
        for (int nt = 0; nt < 8; nt++) {
            int ncol = col0 + wcol * 64 + nt * 8 + c2;
            float b0 = 0.0f, b1 = 0.0f;
            if (bias) { b0 = bias[ncol]; b1 = bias[ncol + 1]; }
            float v0 = acc[mt][nt][0] + b0;
            float v1 = acc[mt][nt][1] + b1;
            float v2 = acc[mt][nt][2] + b0;
            float v3 = acc[mt][nt][3] + b1;
            if (RELU) {
                v0 = fmaxf(v0, 0.0f); v1 = fmaxf(v1, 0.0f);
                v2 = fmaxf(v2, 0.0f); v3 = fmaxf(v3, 0.0f);
            }
            if (RND) {
                v0 = rna(v0); v1 = rna(v1); v2 = rna(v2); v3 = rna(v3);
            }
            *(float2*)(C + (long long)mrow * ldc + ncol) = make_float2(v0, v1);
            *(float2*)(C + (long long)(mrow + 8) * ldc + ncol) = make_float2(v2, v3);
        }
    }
}

// ---------------- fused flash attention -------------------------------------
// grid (S/128, B*H). One CTA: 128 Q rows x one head. 16 KV steps of 64 rows.
__global__ __launch_bounds__(256, 1) void flash_attn(
    const float* __restrict__ Q, const float* __restrict__ K,
    const float* __restrict__ V, const float* __restrict__ mask,
    float* __restrict__ Oc, float* __restrict__ raw15) {
    constexpr int QST = 68, KST = 68, VST = 72, PST = 68;
    extern __shared__ float sm[];
    float* Qs   = sm;                       // 128*68
    float* Ksb  = Qs + 128 * QST;           // 2*64*68
    float* Vsb  = Ksb + 2 * 64 * KST;       // 2*64*72
    float* Ps   = Vsb + 2 * 64 * VST;       // 128*68
    float* Msk  = Ps + 128 * PST;           // 1024
    float* red0 = Msk + 1024;               // 128*4
    float* red1 = red0 + 512;               // 128*4

    const int qb = blockIdx.x, bh = blockIdx.y;
    const int b = bh >> 4, h = bh & 15;
    const float* qp = Q + ((long long)(b * SS + qb * 128)) * DD + h * 64;
    const float* kp = K + ((long long)b * SS) * DD + h * 64;
    const float* vp = V + ((long long)b * SS) * DD + h * 64;
    const float* mp = mask + b * SS;

    const int tid = threadIdx.x, lane = tid & 31, warp = tid >> 5;
    const int wrow = warp >> 2, wcol = warp & 3;
    const int r = lane >> 2, c = lane & 3;

    // prologue loads: mask row, Q tile, KV stage 0
    cp16(Msk + tid * 4, mp + tid * 4);
    #pragma unroll
    for (int i = 0; i < 8; i++) {
        int idx = tid + 256 * i;
        int m = idx >> 4, c4 = (idx & 15) * 4;
        cp16(Qs + m * QST + c4, qp + (long long)m * DD + c4);
    }
    #pragma unroll
    for (int i = 0; i < 4; i++) {
        int idx = tid + 256 * i;
        int n = idx >> 4, c4 = (idx & 15) * 4;
        cp16(Ksb + n * KST + c4, kp + (long long)n * DD + c4);
        cp16(Vsb + n * VST + c4, vp + (long long)n * DD + c4);
    }
    cp_commit();

    float acc_o[4][2][4] = {};
    float mprev[4][2], lsum[4][2];
    #pragma unroll
    for (int mt = 0; mt < 4; mt++)
        #pragma unroll
        for (int hf = 0; hf < 2; hf++) { mprev[mt][hf] = -1e30f; lsum[mt][hf] = 0.0f; }

    for (int j = 0; j < 16; j++) {
        cp_wait<0>();
        __syncthreads();
        const float* ks = Ksb + (j & 1) * 64 * KST;
        const float* vs = Vsb + (j & 1) * 64 * VST;

        // S = Q @ K^T
        float sv[4][2][4] = {};
        #pragma unroll
        for (int k0 = 0; k0 < 64; k0 += 8) {
            uint32_t af[4][4], bf[2][2];
            #pragma unroll
            for (int mt = 0; mt < 4; mt++) {
                int m = wrow * 64 + mt * 16 + r;
                af[mt][0] = *(const uint32_t*)&Qs[m * QST + k0 + c];
                af[mt][1] = *(const uint32_t*)&Qs[(m + 8) * QST + k0 + c];
                af[mt][2] = *(const uint32_t*)&Qs[m * QST + k0 + c + 4];
                af[mt][3] = *(const uint32_t*)&Qs[(m + 8) * QST + k0 + c + 4];
            }
            #pragma unroll
            for (int nt = 0; nt < 2; nt++) {
                int n = wcol * 16 + nt * 8 + r;
                bf[nt][0] = *(const uint32_t*)&ks[n * KST + k0 + c];
                bf[nt][1] = *(const uint32_t*)&ks[n * KST + k0 + c + 4];
            }
            #pragma unroll
            for (int mt = 0; mt < 4; mt++)
                #pragma unroll
                for (int nt = 0; nt < 2; nt++)
                    mma8(sv[mt][nt], af[mt], bf[nt]);
        }

        // scale + mask
        float mk[2][2];
        #pragma unroll
        for (int nt = 0; nt < 2; nt++)
            #pragma unroll
            for (int j2 = 0; j2 < 2; j2++)
                mk[nt][j2] = Msk[j * 64 + wcol * 16 + nt * 8 + 2 * c + j2] * (-1e9f);
        #pragma unroll
        for (int mt = 0; mt < 4; mt++)
            #pragma unroll
            for (int nt = 0; nt < 2; nt++)
                #pragma unroll
                for (int i = 0; i < 4; i++)
                    sv[mt][nt][i] = sv[mt][nt][i] * 0.125f + mk[nt][i & 1];

        // raw score dump for the last head (feeds attn_w output)
        if (h == HH - 1) {
            #pragma unroll
            for (int mt = 0; mt < 4; mt++)
                #pragma unroll
                for (int hf = 0; hf < 2; hf++) {
                    int grow = b * SS + qb * 128 + wrow * 64 + mt * 16 + r + 8 * hf;
                    #pragma unroll
                    for (int nt = 0; nt < 2; nt++) {
                        int col = j * 64 + wcol * 16 + nt * 8 + 2 * c;
                        *(float2*)(raw15 + (long long)grow * SS + col) =
                            make_float2(sv[mt][nt][2 * hf], sv[mt][nt][2 * hf + 1]);
                    }
                }
        }

        // phase A: block row max
        float mnew[4][2];
        #pragma unroll
        for (int mt = 0; mt < 4; mt++)
            #pragma unroll
            for (int hf = 0; hf < 2; hf++) {
                float v = fmaxf(fmaxf(sv[mt][0][2 * hf], sv[mt][0][2 * hf + 1]),
                                fmaxf(sv[mt][1][2 * hf], sv[mt][1][2 * hf + 1]));
                v = fmaxf(v, __shfl_xor_sync(0xffffffffu, v, 1));
                v = fmaxf(v, __shfl_xor_sync(0xffffffffu, v, 2));
                if (c == 0)
                    red0[(wrow * 64 + mt * 16 + r + 8 * hf) * 4 + wcol] = v;
            }
        __syncthreads();
        #pragma unroll
        for (int mt = 0; mt < 4; mt++)
            #pragma unroll
            for (int hf = 0; hf < 2; hf++) {
                int row = wrow * 64 + mt * 16 + r + 8 * hf;
                float mc = fmaxf(fmaxf(red0[row * 4 + 0], red0[row * 4 + 1]),
                                 fmaxf(red0[row * 4 + 2], red0[row * 4 + 3]));
                mnew[mt][hf] = fmaxf(mprev[mt][hf], mc);
            }

        // prefetch next KV stage
        if (j + 1 < 16) {
            float* kd = Ksb + ((j + 1) & 1) * 64 * KST;
            float* vd = Vsb + ((j + 1) & 1) * 64 * VST;
            #pragma unroll
            for (int i = 0; i < 4; i++) {
                int idx = tid + 256 * i;
                int n = idx >> 4, c4 = (idx & 15) * 4;
                cp16(kd + n * KST + c4, kp + (long long)((j + 1) * 64 + n) * DD + c4);
                cp16(vd + n * VST + c4, vp + (long long)((j + 1) * 64 + n) * DD + c4);
            }
            cp_commit();
        }

        // phase B: exp, row sums, P -> SMEM (tf32-rounded)
        float psum[4][2] = {};
        #pragma unroll
        for (int mt = 0; mt < 4; mt++)
            #pragma unroll
            for (int nt = 0; nt < 2; nt++)
                #pragma unroll
                for (int i = 0; i < 4; i++) {
                    float p = __expf(sv[mt][nt][i] - mnew[mt][i >> 1]);
                    sv[mt][nt][i] = p;
                    psum[mt][i >> 1] += p;
                }
        #pragma unroll
        for (int mt = 0; mt < 4; mt++)
            #pragma unroll
            for (int hf = 0; hf < 2; hf++) {
                float v = psum[mt][hf];
                v += __shfl_xor_sync(0xffffffffu, v, 1);
                v += __shfl_xor_sync(0xffffffffu, v, 2);
                if (c == 0)
                    red1[(wrow * 64 + mt * 16 + r + 8 * hf) * 4 + wcol] = v;
            }
        #pragma unroll
        for (int mt = 0; mt < 4; mt++)
            #pragma unroll
            for (int hf = 0; hf < 2; hf++) {
                int row = wrow * 64 + mt * 16 + r + 8 * hf;
                #pragma unroll
                for (int nt = 0; nt < 2; nt++) {
                    int col = wcol * 16 + nt * 8 + 2 * c;
                    *(float2*)&Ps[row * PST + col] =
                        make_float2(rna(sv[mt][nt][2 * hf]), rna(sv[mt][nt][2 * hf + 1]));
                }
            }
        __syncthreads();

        // finalize stats, rescale O
        #pragma unroll
        for (int mt = 0; mt < 4; mt++)
            #pragma unroll
            for (int hf = 0; hf < 2; hf++) {
                int row = wrow * 64 + mt * 16 + r + 8 * hf;
                float sumb = red1[row * 4 + 0] + red1[row * 4 + 1] +
                             red1[row * 4 + 2] + red1[row * 4 + 3];
                float alpha = __expf(mprev[mt][hf] - mnew[mt][hf]);
                lsum[mt][hf] = lsum[mt][hf] * alpha + sumb;
                mprev[mt][hf] = mnew[mt][hf];
                #pragma unroll
                for (int nt = 0; nt < 2; nt++) {
                    acc_o[mt][nt][2 * hf] *= alpha;
                    acc_o[mt][nt][2 * hf + 1] *= alpha;
                }
            }

        // O += P @ V
        #pragma unroll
        for (int k0 = 0; k0 < 64; k0 += 8) {
            uint32_t af[4][4], bf[2][2];
            #pragma unroll
            for (int mt = 0; mt < 4; mt++) {
                int m = wrow * 64 + mt * 16 + r;
                af[mt][0] = *(const uint32_t*)&Ps[m * PST + k0 + c];
                af[mt][1] = *(const uint32_t*)&Ps[(m + 8) * PST + k0 + c];
                af[mt][2] = *(const uint32_t*)&Ps[m * PST + k0 + c + 4];
                af[mt][3] = *(const uint32_t*)&Ps[(m + 8) * PST + k0 + c + 4];
            }
            #pragma unroll
            for (int nt = 0; nt < 2; nt++) {
                int n = wcol * 16 + nt * 8 + r;
                bf[nt][0] = *(const uint32_t*)&vs[(k0 + c) * VST + n];
                bf[nt][1] = *(const uint32_t*)&vs[(k0 + c + 4) * VST + n];
            }
            #pragma unroll
            for (int mt = 0; mt < 4; mt++)
                #pragma unroll
                for (int nt = 0; nt < 2; nt++)
                    mma8(acc_o[mt][nt], af[mt], bf[nt]);
        }
    }

    // epilogue: O / l -> concat (rounded, feeds w0 GEMM)
    #pragma unroll
    for (int mt = 0; mt < 4; mt++) {
        #pragma unroll
        for (int hf = 0; hf < 2; hf++) {
            float inv = 1.0f / lsum[mt][hf];
            int grow = b * SS + qb * 128 + wrow * 64 + mt * 16 + r + 8 * hf;
            #pragma unroll
            for (int nt = 0; nt < 2; nt++) {
                int col = h * 64 + wcol * 16 + nt * 8 + 2 * c;
                *(float2*)(Oc + (long long)grow * DD + col) =
                    make_float2(rna(acc_o[mt][nt][2 * hf] * inv),
                                rna(acc_o[mt][nt][2 * hf + 1] * inv));
            }
        }
    }
}

// ---------------- softmax of dumped last-head scores -> out_attn -----------
__global__ __launch_bounds__(256) void softmax_out(
    const float* __restrict__ raw, float* __restrict__ out_attn) {
    long long rr = blockIdx.x;               // 0 .. B*S-1
    const float* row = raw + rr * SS;
    float* orow = out_attn + rr * SS;
    int tid = threadIdx.x;

    float vals[4];
    float mx = -1e30f;
    #pragma unroll
    for (int i = 0; i < 4; i++) {
        float v = row[tid + 256 * i];
        vals[i] = v;
        mx = fmaxf(mx, v);
    }
    __shared__ float red[256];
    red[tid] = mx;
    __syncthreads();
    for (int off = 128; off > 0; off >>= 1) {
        if (tid < off) red[tid] = fmaxf(red[tid], red[tid + off]);
        __syncthreads();
    }
    mx = red[0];
    __syncthreads();
    float sum = 0.0f;
    #pragma unroll
    for (int i = 0; i < 4; i++) {
        vals[i] = __expf(vals[i] - mx);
        sum += vals[i];
    }
    red[tid] = sum;
    __syncthreads();
    for (int off = 128; off > 0; off >>= 1) {
        if (tid < off) red[tid] += red[tid + off];
        __syncthreads();
    }
    float inv = 1.0f / red[0];
    #pragma unroll
    for (int i = 0; i < 4; i++)
        orow[tid + 256 * i] = vals[i] * inv;
}

// ---------------- residual add + layernorm (optional rounded copy) ---------
__global__ __launch_bounds__(256) void add_ln_kernel(
    const float* __restrict__ xa, const float* __restrict__ xb,
    const float* __restrict__ g, const float* __restrict__ bt,
    float* __restrict__ out, float* __restrict__ out_r) {
    long long rr = blockIdx.x;               // 0 .. B*S-1
    const float* pa = xa + rr * DD;
    const float* pb = xb + rr * DD;
    float* po = out + rr * DD;
    int tid = threadIdx.x;

    float v[4];
    float sum = 0.0f, sq = 0.0f;
    #pragma unroll
    for (int i = 0; i < 4; i++) {
        int cc = tid + 256 * i;
        float x = pa[cc] + pb[cc];
        v[i] = x;
        sum += x;
        sq += x * x;
    }
    __shared__ float r1[256], r2[256];
    r1[tid] = sum;
    r2[tid] = sq;
    __syncthreads();
    for (int off = 128; off > 0; off >>= 1) {
        if (tid < off) { r1[tid] += r1[tid + off]; r2[tid] += r2[tid + off]; }
        __syncthreads();
    }
    float mu = r1[0] * (1.0f / DD);
    float var = r2[0] * (1.0f / DD) - mu * mu;
    float rstd = rsqrtf(var + 1e-6f);

    #pragma unroll
    for (int i = 0; i < 4; i++) {
        int cc = tid + 256 * i;
        float y = (v[i] - mu) * rstd * g[cc] + bt[cc];
        po[cc] = y;
        if (out_r) out_r[rr * DD + cc] = rna(y);
    }
}

// ---------------- launch ----------------------------------------------------
static int g_attr_set = 0;

extern "C" void kernel_launch(void* const* d_in, const int* in_sizes, int n_in,
                              void* d_out, int out_size) {
    const float* x_v   = (const float*)d_in[0];
    const float* x_k   = (const float*)d_in[1];
    const float* x_q   = (const float*)d_in[2];
    const float* mask  = (const float*)d_in[3];
    const float* wq    = (const float*)d_in[4];
    const float* bq    = (const float*)d_in[5];
    const float* wk    = (const float*)d_in[6];
    const float* bk    = (const float*)d_in[7];
    const float* wv    = (const float*)d_in[8];
    const float* bv    = (const float*)d_in[9];
    const float* w0    = (const float*)d_in[10];
    const float* b0    = (const float*)d_in[11];
    const float* ln1_g = (const float*)d_in[12];
    const float* ln1_b = (const float*)d_in[13];
    const float* ff1_w = (const float*)d_in[14];
    const float* ff1_b = (const float*)d_in[15];
    const float* ff2_w = (const float*)d_in[16];
    const float* ff2_b = (const float*)d_in[17];
    const float* ln2_g = (const float*)d_in[18];
    const float* ln2_b = (const float*)d_in[19];

    float* out = (float*)d_out;
    float* out_attn = out + (long long)BB * SS * DD;

    const int SM_G3 = 3 * (128 * 36 + 32 * 136) * 4;   // 107520
    const int SM_FL = (128 * 68 + 2 * 64 * 68 + 2 * 64 * 72 + 128 * 68
                       + 1024 + 512 + 512) * 4;        // 149504

    if (!g_attr_set) {
        cudaFuncSetAttribute(gemm_tc3<0, 0>,
                             cudaFuncAttributeMaxDynamicSharedMemorySize, SM_G3);
        cudaFuncSetAttribute(gemm_tc3<0, 1>,
                             cudaFuncAttributeMaxDynamicSharedMemorySize, SM_G3);
        cudaFuncSetAttribute(gemm_tc3<1, 1>,
                             cudaFuncAttributeMaxDynamicSharedMemorySize, SM_G3);
        cudaFuncSetAttribute(flash_attn,
                             cudaFuncAttributeMaxDynamicSharedMemorySize, SM_FL);
        g_attr_set = 1;
    }

    float *pxq, *pxk, *pxv, *pw0r, *pff1r, *pff2r;
    float *pwq, *pwk, *pwv, *pq, *pk, *pv, *praw, *pconcat, *pffn1;
    cudaGetSymbolAddress((void**)&pxq, g_xq);
    cudaGetSymbolAddress((void**)&pxk, g_xk);
    cudaGetSymbolAddress((void**)&pxv, g_xv);
    cudaGetSymbolAddress((void**)&pw0r, g_w0r);
    cudaGetSymbolAddress((void**)&pff1r, g_ff1r);
    cudaGetSymbolAddress((void**)&pff2r, g_ff2r);
    cudaGetSymbolAddress((void**)&pwq, g_wq);
    cudaGetSymbolAddress((void**)&pwk, g_wk);
    cudaGetSymbolAddress((void**)&pwv, g_wv);
    cudaGetSymbolAddress((void**)&pq, g_q);
    cudaGetSymbolAddress((void**)&pk, g_k);
    cudaGetSymbolAddress((void**)&pv, g_v);
    cudaGetSymbolAddress((void**)&praw, g_att_raw);
    cudaGetSymbolAddress((void**)&pconcat, g_concat);
    cudaGetSymbolAddress((void**)&pffn1, g_ffn1);

    dim3 blk(256);
    dim3 gblk(128);
    const int MT = BB * SS;                          // 4096 token rows

    // prep: tf32-round inputs + weights
    round_copy<<<(BB * SS * DD) / 1024, blk>>>(x_q, pxq);
    round_copy<<<(BB * SS * DD) / 1024, blk>>>(x_k, pxk);
    round_copy<<<(BB * SS * DD) / 1024, blk>>>(x_v, pxv);
    round_copy<<<(DD * DD) / 1024, blk>>>(w0, pw0r);
    round_copy<<<(DD * DFF) / 1024, blk>>>(ff1_w, pff1r);
    round_copy<<<(DFF * DD) / 1024, blk>>>(ff2_w, pff2r);
    repack_kernel<<<(DD * DD) / 256, blk>>>(wq, wk, wv);

    // q/k/v projections (rounded outputs feed attention MMAs)
    gemm_tc3<0, 1><<<dim3(8, 32), gblk, SM_G3>>>(pxq, pwq, bq, pq, DD, DD, DD, DD);
    gemm_tc3<0, 1><<<dim3(8, 32), gblk, SM_G3>>>(pxk, pwk, bk, pk, DD, DD, DD, DD);
    gemm_tc3<0, 1><<<dim3(8, 32), gblk, SM_G3>>>(pxv, pwv, bv, pv, DD, DD, DD, DD);

    // fused attention: scores + softmax + P@V; dumps last-head raw scores
    flash_attn<<<dim3(SS / 128, BB * HH), blk, SM_FL>>>(pq, pk, pv, mask, pconcat, praw);

    // last-head attention weights -> d_out second half
    softmax_out<<<BB * SS, blk>>>(praw, out_attn);

    // mha_out = concat @ w0 + b0  (reuse g_xq)
    gemm_tc3<0, 0><<<dim3(8, 32), gblk, SM_G3>>>(pconcat, pw0r, b0, pxq, DD, DD, DD, DD);

    // sub1 = LN1(x_q + mha_out): exact -> g_k, rounded -> g_xk
    add_ln_kernel<<<MT, blk>>>(x_q, pxq, ln1_g, ln1_b, pk, pxk);

    // ffn1 = relu(sub1 @ ff1_w + ff1_b), rounded
    gemm_tc3<1, 1><<<dim3(32, 32), gblk, SM_G3>>>(pxk, pff1r, ff1_b, pffn1, DD, DD, DFF, DFF);

    // ffn2 = ffn1 @ ff2_w + ff2_b  (reuse g_xv)
    gemm_tc3<0, 0><<<dim3(8, 32), gblk, SM_G3>>>(pffn1, pff2r, ff2_b, pxv, DFF, DFF, DD, DD);

    // out = LN2(sub1 + ffn2) -> d_out first half
    add_ln_kernel<<<MT, blk>>>(pk, pxv, ln2_g, ln2_b, out, nullptr);
}

// round 6
// speedup vs baseline: 1.0139x; 1.0139x over previous
#include <cuda_runtime.h>
#include <math.h>
#include <stdint.h>

#define BB 4
#define SS 1024
#define DD 1024
#define HH 16
#define DK 64
#define DFF 4096

// ---------------- scratch (device globals; no allocations allowed) ----------
__device__ float g_xq[BB * SS * DD];      // rounded x_q; reused as mha_out
__device__ float g_xk[BB * SS * DD];      // rounded x_k; reused as sub1_rounded
__device__ float g_xv[BB * SS * DD];      // rounded x_v; reused as ffn2 out
__device__ float g_w0r[DD * DD];
__device__ float g_ff1r[DD * DFF];
__device__ float g_ff2r[DFF * DD];
__device__ float g_wq[DD * DD];
__device__ float g_wk[DD * DD];
__device__ float g_wv[DD * DD];
__device__ float g_q[BB * SS * DD];       // q [B,S,H,DK]
__device__ float g_k[BB * SS * DD];       // k; reused as sub1 (exact)
__device__ float g_v[BB * SS * DD];       // v
__device__ float g_att_raw[(long long)BB * SS * SS]; // last-head raw scores (16MB)
__device__ float g_concat[BB * SS * DD];  // flash O output
__device__ float g_ffn1[(long long)BB * SS * DFF];

// ---------------- helpers ----------------------------------------------------
__device__ __forceinline__ void cp16(float* smem_dst, const float* gmem_src) {
    uint32_t s = (uint32_t)__cvta_generic_to_shared(smem_dst);
    asm volatile("cp.async.ca.shared.global [%0], [%1], 16;" :: "r"(s), "l"(gmem_src));
}
__device__ __forceinline__ void cp_commit() {
    asm volatile("cp.async.commit_group;");
}
template <int N>
__device__ __forceinline__ void cp_wait() {
    asm volatile("cp.async.wait_group %0;" :: "n"(N));
}
__device__ __forceinline__ float rna(float x) {
    uint32_t u;
    asm("cvt.rna.tf32.f32 %0, %1;" : "=r"(u) : "f"(x));
    return __uint_as_float(u);
}
__device__ __forceinline__ void mma8(float* d, const uint32_t* a, const uint32_t* b) {
    asm volatile(
        "mma.sync.aligned.m16n8k8.row.col.f32.tf32.tf32.f32 "
        "{%0,%1,%2,%3}, {%4,%5,%6,%7}, {%8,%9}, {%0,%1,%2,%3};"
        : "+f"(d[0]), "+f"(d[1]), "+f"(d[2]), "+f"(d[3])
        : "r"(a[0]), "r"(a[1]), "r"(a[2]), "r"(a[3]), "r"(b[0]), "r"(b[1]));
}

// ---------------- prep: round-to-nearest tf32 copies -------------------------
__global__ void round_copy(const float* __restrict__ src, float* __restrict__ dst) {
    int i = blockIdx.x * 256 + threadIdx.x;
    float4 v = ((const float4*)src)[i];
    v.x = rna(v.x); v.y = rna(v.y); v.z = rna(v.z); v.w = rna(v.w);
    ((float4*)dst)[i] = v;
}

// repack per-head weights [H,D,DK] -> [D, H*DK], rounded
__global__ void repack_kernel(const float* __restrict__ wq,
                              const float* __restrict__ wk,
                              const float* __restrict__ wv) {
    int idx = blockIdx.x * 256 + threadIdx.x;     // over D*D
    int d = idx >> 10;
    int c = idx & 1023;                            // c = h*DK + k
    int src = ((c >> 6) << 16) | (d << 6) | (c & 63);
    g_wq[idx] = rna(wq[src]);
    g_wk[idx] = rna(wk[src]);
    g_wv[idx] = rna(wv[src]);
}

// ---------------- TF32 GEMM: 256 threads, 8 warps (2x4), warp tile 64x32 ----
// 3-stage cp.async ring, single __syncthreads per k-tile, early issue.
template <int RELU, int RND>
__global__ __launch_bounds__(256, 2) void gemm_tc2(
    const float* __restrict__ A, const float* __restrict__ Bm,
    const float* __restrict__ bias, float* __restrict__ C,
    int K, int lda, int ldb, int ldc) {
    constexpr int BM = 128, BN = 128, BK = 32;
    constexpr int AST = BK + 4;               // 36
    constexpr int BST = BN + 8;               // 136
    constexpr int STG = BM * AST + BK * BST;  // 8960 floats per stage
    constexpr int WM = 64, WN = 32;
    constexpr int MT = 4, NT = 4;

    extern __shared__ float sm[];             // [3][STG]

    const int tid = threadIdx.x;
    const int lane = tid & 31, warp = tid >> 5;
    const int wrow = warp >> 2, wcol = warp & 3;
    const int row0 = blockIdx.y * BM, col0 = blockIdx.x * BN;
    const int nk = K / BK;

    auto issue = [&](int kt) {
        float* as = sm + (kt % 3) * STG;
        float* bs = as + BM * AST;
        #pragma unroll
        for (int i = 0; i < 4; i++) {
            int idx = tid + 256 * i;
            int m = idx >> 3, c4 = (idx & 7) * 4;
            cp16(as + m * AST + c4, A + (long long)(row0 + m) * lda + kt * BK + c4);
        }
        #pragma unroll
        for (int i = 0; i < 4; i++) {
            int idx = tid + 256 * i;
            int kk = idx >> 5, c4 = (idx & 31) * 4;
            cp16(bs + kk * BST + c4, Bm + (long long)(kt * BK + kk) * ldb + col0 + c4);
        }
        cp_commit();
    };

    float acc[MT][NT][4] = {};

    issue(0);
    if (nk > 1) issue(1);

    const int r = lane >> 2, c = lane & 3;
    for (int kt = 0; kt < nk; kt++) {
        if (kt == nk - 1) cp_wait<0>(); else cp_wait<1>();
        __syncthreads();
        if (kt + 2 < nk) issue(kt + 2);   // buffer (kt+2)%3 is free: not read, not in flight

        const float* as = sm + (kt % 3) * STG;
        const float* bs = as + BM * AST;
        #pragma unroll
        for (int ks = 0; ks < 4; ks++) {
            const int k0 = ks * 8;
            uint32_t af[MT][4], bf[NT][2];
            #pragma unroll
            for (int mt = 0; mt < MT; mt++) {
                int m = wrow * WM + mt * 16 + r;
                af[mt][0] = *(const uint32_t*)&as[m * AST + k0 + c];
                af[mt][1] = *(const uint32_t*)&as[(m + 8) * AST + k0 + c];
                af[mt][2] = *(const uint32_t*)&as[m * AST + k0 + c + 4];
                af[mt][3] = *(const uint32_t*)&as[(m + 8) * AST + k0 + c + 4];
            }
            #pragma unroll
            for (int nt = 0; nt < NT; nt++) {
                int n = wcol * WN + nt * 8 + r;
                bf[nt][0] = *(const uint32_t*)&bs[(k0 + c) * BST + n];
                bf[nt][1] = *(const uint32_t*)&bs[(k0 + c + 4) * BST + n];
            }
            #pragma unroll
            for (int mt = 0; mt < MT; mt++)
                #pragma unroll
                for (int nt = 0; nt < NT; nt++)
                    mma8(acc[mt][nt], af[mt], bf[nt]);
        }
        // no trailing barrier: next iteration's wait+sync protects reuse
    }

    const int c2 = (lane & 3) * 2;
    #pragma unroll
    for (int mt = 0; mt < MT; mt++) {
        int mrow = row0 + wrow * WM + mt * 16 + r;
        #pragma unroll
        for (int nt = 0; nt < NT; nt++) {
            int ncol = col0 + wcol * WN + nt * 8 + c2;
            float b0 = 0.0f, b1 = 0.0f;
            if (bias) { b0 = bias[ncol]; b1 = bias[ncol + 1]; }
            float v0 = acc[mt][nt][0] + b0;
            float v1 = acc[mt][nt][1] + b1;
            float v2 = acc[mt][nt][2] + b0;
            float v3 = acc[mt][nt][3] + b1;
            if (RELU) {
                v0 = fmaxf(v0, 0.0f); v1 = fmaxf(v1, 0.0f);
                v2 = fmaxf(v2, 0.0f); v3 = fmaxf(v3, 0.0f);
            }
            if (RND) {
                v0 = rna(v0); v1 = rna(v1); v2 = rna(v2); v3 = rna(v3);
            }
            *(float2*)(C + (long long)mrow * ldc + ncol) = make_float2(v0, v1);
            *(float2*)(C + (long long)(mrow + 8) * ldc + ncol) = make_float2(v2, v3);
        }
    }
}

// ---------------- fused flash attention -------------------------------------
// grid (S/128, B*H). One CTA: 128 Q rows x one head. 16 KV steps of 64 rows.
__global__ __launch_bounds__(256, 1) void flash_attn(
    const float* __restrict__ Q, const float* __restrict__ K,
    const float* __restrict__ V, const float* __restrict__ mask,
    float* __restrict__ Oc, float* __restrict__ raw15) {
    constexpr int QST = 68, KST = 68, VST = 72, PST = 68;
    extern __shared__ float sm[];
    float* Qs   = sm;                       // 128*68
    float* Ksb  = Qs + 128 * QST;           // 2*64*68
    float* Vsb  = Ksb + 2 * 64 * KST;       // 2*64*72
    float* Ps   = Vsb + 2 * 64 * VST;       // 128*68
    float* Msk  = Ps + 128 * PST;           // 1024
    float* red0 = Msk + 1024;               // 128*4
    float* red1 = red0 + 512;               // 128*4

    const int qb = blockIdx.x, bh = blockIdx.y;
    const int b = bh >> 4, h = bh & 15;
    const float* qp = Q + ((long long)(b * SS + qb * 128)) * DD + h * 64;
    const float* kp = K + ((long long)b * SS) * DD + h * 64;
    const float* vp = V + ((long long)b * SS) * DD + h * 64;
    const float* mp = mask + b * SS;

    const int tid = threadIdx.x, lane = tid & 31, warp = tid >> 5;
    const int wrow = warp >> 2, wcol = warp & 3;
    const int r = lane >> 2, c = lane & 3;

    // prologue loads: mask row, Q tile, KV stage 0
    cp16(Msk + tid * 4, mp + tid * 4);
    #pragma unroll
    for (int i = 0; i < 8; i++) {
        int idx = tid + 256 * i;
        int m = idx >> 4, c4 = (idx & 15) * 4;
        cp16(Qs + m * QST + c4, qp + (long long)m * DD + c4);
    }
    #pragma unroll
    for (int i = 0; i < 4; i++) {
        int idx = tid + 256 * i;
        int n = idx >> 4, c4 = (idx & 15) * 4;
        cp16(Ksb + n * KST + c4, kp + (long long)n * DD + c4);
        cp16(Vsb + n * VST + c4, vp + (long long)n * DD + c4);
    }
    cp_commit();

    float acc_o[4][2][4] = {};
    float mprev[4][2], lsum[4][2];
    #pragma unroll
    for (int mt = 0; mt < 4; mt++)
        #pragma unroll
        for (int hf = 0; hf < 2; hf++) { mprev[mt][hf] = -1e30f; lsum[mt][hf] = 0.0f; }

    for (int j = 0; j < 16; j++) {
        cp_wait<0>();
        __syncthreads();
        const float* ks = Ksb + (j & 1) * 64 * KST;
        const float* vs = Vsb + (j & 1) * 64 * VST;

        // S = Q @ K^T
        float sv[4][2][4] = {};
        #pragma unroll
        for (int k0 = 0; k0 < 64; k0 += 8) {
            uint32_t af[4][4], bf[2][2];
            #pragma unroll
            for (int mt = 0; mt < 4; mt++) {
                int m = wrow * 64 + mt * 16 + r;
                af[mt][0] = *(const uint32_t*)&Qs[m * QST + k0 + c];
                af[mt][1] = *(const uint32_t*)&Qs[(m + 8) * QST + k0 + c];
                af[mt][2] = *(const uint32_t*)&Qs[m * QST + k0 + c + 4];
                af[mt][3] = *(const uint32_t*)&Qs[(m + 8) * QST + k0 + c + 4];
            }
            #pragma unroll
            for (int nt = 0; nt < 2; nt++) {
                int n = wcol * 16 + nt * 8 + r;
                bf[nt][0] = *(const uint32_t*)&ks[n * KST + k0 + c];
                bf[nt][1] = *(const uint32_t*)&ks[n * KST + k0 + c + 4];
            }
            #pragma unroll
            for (int mt = 0; mt < 4; mt++)
                #pragma unroll
                for (int nt = 0; nt < 2; nt++)
                    mma8(sv[mt][nt], af[mt], bf[nt]);
        }

        // scale + mask
        float mk[2][2];
        #pragma unroll
        for (int nt = 0; nt < 2; nt++)
            #pragma unroll
            for (int j2 = 0; j2 < 2; j2++)
                mk[nt][j2] = Msk[j * 64 + wcol * 16 + nt * 8 + 2 * c + j2] * (-1e9f);
        #pragma unroll
        for (int mt = 0; mt < 4; mt++)
            #pragma unroll
            for (int nt = 0; nt < 2; nt++)
                #pragma unroll
                for (int i = 0; i < 4; i++)
                    sv[mt][nt][i] = sv[mt][nt][i] * 0.125f + mk[nt][i & 1];

        // raw score dump for the last head (feeds attn_w output)
        if (h == HH - 1) {
            #pragma unroll
            for (int mt = 0; mt < 4; mt++)
                #pragma unroll
                for (int hf = 0; hf < 2; hf++) {
                    int grow = b * SS + qb * 128 + wrow * 64 + mt * 16 + r + 8 * hf;
                    #pragma unroll
                    for (int nt = 0; nt < 2; nt++) {
                        int col = j * 64 + wcol * 16 + nt * 8 + 2 * c;
                        *(float2*)(raw15 + (long long)grow * SS + col) =
                            make_float2(sv[mt][nt][2 * hf], sv[mt][nt][2 * hf + 1]);
                    }
                }
        }

        // phase A: block row max
        float mnew[4][2];
        #pragma unroll
        for (int mt = 0; mt < 4; mt++)
            #pragma unroll
            for (int hf = 0; hf < 2; hf++) {
                float v = fmaxf(fmaxf(sv[mt][0][2 * hf], sv[mt][0][2 * hf + 1]),
                                fmaxf(sv[mt][1][2 * hf], sv[mt][1][2 * hf + 1]));
                v = fmaxf(v, __shfl_xor_sync(0xffffffffu, v, 1));
                v = fmaxf(v, __shfl_xor_sync(0xffffffffu, v, 2));
                if (c == 0)
                    red0[(wrow * 64 + mt * 16 + r + 8 * hf) * 4 + wcol] = v;
            }
        __syncthreads();
        #pragma unroll
        for (int mt = 0; mt < 4; mt++)
            #pragma unroll
            for (int hf = 0; hf < 2; hf++) {
                int row = wrow * 64 + mt * 16 + r + 8 * hf;
                float mc = fmaxf(fmaxf(red0[row * 4 + 0], red0[row * 4 + 1]),
                                 fmaxf(red0[row * 4 + 2], red0[row * 4 + 3]));
                mnew[mt][hf] = fmaxf(mprev[mt][hf], mc);
            }

        // prefetch next KV stage
        if (j + 1 < 16) {
            float* kd = Ksb + ((j + 1) & 1) * 64 * KST;
            float* vd = Vsb + ((j + 1) & 1) * 64 * VST;
            #pragma unroll
            for (int i = 0; i < 4; i++) {
                int idx = tid + 256 * i;
                int n = idx >> 4, c4 = (idx & 15) * 4;
                cp16(kd + n * KST + c4, kp + (long long)((j + 1) * 64 + n) * DD + c4);
                cp16(vd + n * VST + c4, vp + (long long)((j + 1) * 64 + n) * DD + c4);
            }
            cp_commit();
        }

        // phase B: exp, row sums, P -> SMEM (tf32-rounded)
        float psum[4][2] = {};
        #pragma unroll
        for (int mt = 0; mt < 4; mt++)
            #pragma unroll
            for (int nt = 0; nt < 2; nt++)
                #pragma unroll
                for (int i = 0; i < 4; i++) {
                    float p = __expf(sv[mt][nt][i] - mnew[mt][i >> 1]);
                    sv[mt][nt][i] = p;
                    psum[mt][i >> 1] += p;
                }
        #pragma unroll
        for (int mt = 0; mt < 4; mt++)
            #pragma unroll
            for (int hf = 0; hf < 2; hf++) {
                float v = psum[mt][hf];
                v += __shfl_xor_sync(0xffffffffu, v, 1);
                v += __shfl_xor_sync(0xffffffffu, v, 2);
                if (c == 0)
                    red1[(wrow * 64 + mt * 16 + r + 8 * hf) * 4 + wcol] = v;
            }
        #pragma unroll
        for (int mt = 0; mt < 4; mt++)
            #pragma unroll
            for (int hf = 0; hf < 2; hf++) {
                int row = wrow * 64 + mt * 16 + r + 8 * hf;
                #pragma unroll
                for (int nt = 0; nt < 2; nt++) {
                    int col = wcol * 16 + nt * 8 + 2 * c;
                    *(float2*)&Ps[row * PST + col] =
                        make_float2(rna(sv[mt][nt][2 * hf]), rna(sv[mt][nt][2 * hf + 1]));
                }
            }
        __syncthreads();

        // finalize stats, rescale O
        #pragma unroll
        for (int mt = 0; mt < 4; mt++)
            #pragma unroll
            for (int hf = 0; hf < 2; hf++) {
                int row = wrow * 64 + mt * 16 + r + 8 * hf;
                float sumb = red1[row * 4 + 0] + red1[row * 4 + 1] +
                             red1[row * 4 + 2] + red1[row * 4 + 3];
                float alpha = __expf(mprev[mt][hf] - mnew[mt][hf]);
                lsum[mt][hf] = lsum[mt][hf] * alpha + sumb;
                mprev[mt][hf] = mnew[mt][hf];
                #pragma unroll
                for (int nt = 0; nt < 2; nt++) {
                    acc_o[mt][nt][2 * hf] *= alpha;
                    acc_o[mt][nt][2 * hf + 1] *= alpha;
                }
            }

        // O += P @ V
        #pragma unroll
        for (int k0 = 0; k0 < 64; k0 += 8) {
            uint32_t af[4][4], bf[2][2];
            #pragma unroll
            for (int mt = 0; mt < 4; mt++) {
                int m = wrow * 64 + mt * 16 + r;
                af[mt][0] = *(const uint32_t*)&Ps[m * PST + k0 + c];
                af[mt][1] = *(const uint32_t*)&Ps[(m + 8) * PST + k0 + c];
                af[mt][2] = *(const uint32_t*)&Ps[m * PST + k0 + c + 4];
                af[mt][3] = *(const uint32_t*)&Ps[(m + 8) * PST + k0 + c + 4];
            }
            #pragma unroll
            for (int nt = 0; nt < 2; nt++) {
                int n = wcol * 16 + nt * 8 + r;
                bf[nt][0] = *(const uint32_t*)&vs[(k0 + c) * VST + n];
                bf[nt][1] = *(const uint32_t*)&vs[(k0 + c + 4) * VST + n];
            }
            #pragma unroll
            for (int mt = 0; mt < 4; mt++)
                #pragma unroll
                for (int nt = 0; nt < 2; nt++)
                    mma8(acc_o[mt][nt], af[mt], bf[nt]);
        }
    }

    // epilogue: O / l -> concat (rounded, feeds w0 GEMM)
    #pragma unroll
    for (int mt = 0; mt < 4; mt++) {
        #pragma unroll
        for (int hf = 0; hf < 2; hf++) {
            float inv = 1.0f / lsum[mt][hf];
            int grow = b * SS + qb * 128 + wrow * 64 + mt * 16 + r + 8 * hf;
            #pragma unroll
            for (int nt = 0; nt < 2; nt++) {
                int col = h * 64 + wcol * 16 + nt * 8 + 2 * c;
                *(float2*)(Oc + (long long)grow * DD + col) =
                    make_float2(rna(acc_o[mt][nt][2 * hf] * inv),
                                rna(acc_o[mt][nt][2 * hf + 1] * inv));
            }
        }
    }
}

// ---------------- softmax of dumped last-head scores -> out_attn -----------
__global__ __launch_bounds__(256) void softmax_out(
    const float* __restrict__ raw, float* __restrict__ out_attn) {
    long long rr = blockIdx.x;               // 0 .. B*S-1
    const float* row = raw + rr * SS;
    float* orow = out_attn + rr * SS;
    int tid = threadIdx.x;

    float vals[4];
    float mx = -1e30f;
    #pragma unroll
    for (int i = 0; i < 4; i++) {
        float v = row[tid + 256 * i];
        vals[i] = v;
        mx = fmaxf(mx, v);
    }
    __shared__ float red[256];
    red[tid] = mx;
    __syncthreads();
    for (int off = 128; off > 0; off >>= 1) {
        if (tid < off) red[tid] = fmaxf(red[tid], red[tid + off]);
        __syncthreads();
    }
    mx = red[0];
    __syncthreads();
    float sum = 0.0f;
    #pragma unroll
    for (int i = 0; i < 4; i++) {
        vals[i] = __expf(vals[i] - mx);
        sum += vals[i];
    }
    red[tid] = sum;
    __syncthreads();
    for (int off = 128; off > 0; off >>= 1) {
        if (tid < off) red[tid] += red[tid + off];
        __syncthreads();
    }
    float inv = 1.0f / red[0];
    #pragma unroll
    for (int i = 0; i < 4; i++)
        orow[tid + 256 * i] = vals[i] * inv;
}

// ---------------- residual add + layernorm (optional rounded copy) ---------
__global__ __launch_bounds__(256) void add_ln_kernel(
    const float* __restrict__ xa, const float* __restrict__ xb,
    const float* __restrict__ g, const float* __restrict__ bt,
    float* __restrict__ out, float* __restrict__ out_r) {
    long long rr = blockIdx.x;               // 0 .. B*S-1
    const float* pa = xa + rr * DD;
    const float* pb = xb + rr * DD;
    float* po = out + rr * DD;
    int tid = threadIdx.x;

    float v[4];
    float sum = 0.0f, sq = 0.0f;
    #pragma unroll
    for (int i = 0; i < 4; i++) {
        int cc = tid + 256 * i;
        float x = pa[cc] + pb[cc];
        v[i] = x;
        sum += x;
        sq += x * x;
    }
    __shared__ float r1[256], r2[256];
    r1[tid] = sum;
    r2[tid] = sq;
    __syncthreads();
    for (int off = 128; off > 0; off >>= 1) {
        if (tid < off) { r1[tid] += r1[tid + off]; r2[tid] += r2[tid + off]; }
        __syncthreads();
    }
    float mu = r1[0] * (1.0f / DD);
    float var = r2[0] * (1.0f / DD) - mu * mu;
    float rstd = rsqrtf(var + 1e-6f);

    #pragma unroll
    for (int i = 0; i < 4; i++) {
        int cc = tid + 256 * i;
        float y = (v[i] - mu) * rstd * g[cc] + bt[cc];
        po[cc] = y;
        if (out_r) out_r[rr * DD + cc] = rna(y);
    }
}

// ---------------- launch ----------------------------------------------------
static int g_attr_set = 0;

extern "C" void kernel_launch(void* const* d_in, const int* in_sizes, int n_in,
                              void* d_out, int out_size) {
    const float* x_v   = (const float*)d_in[0];
    const float* x_k   = (const float*)d_in[1];
    const float* x_q   = (const float*)d_in[2];
    const float* mask  = (const float*)d_in[3];
    const float* wq    = (const float*)d_in[4];
    const float* bq    = (const float*)d_in[5];
    const float* wk    = (const float*)d_in[6];
    const float* bk    = (const float*)d_in[7];
    const float* wv    = (const float*)d_in[8];
    const float* bv    = (const float*)d_in[9];
    const float* w0    = (const float*)d_in[10];
    const float* b0    = (const float*)d_in[11];
    const float* ln1_g = (const float*)d_in[12];
    const float* ln1_b = (const float*)d_in[13];
    const float* ff1_w = (const float*)d_in[14];
    const float* ff1_b = (const float*)d_in[15];
    const float* ff2_w = (const float*)d_in[16];
    const float* ff2_b = (const float*)d_in[17];
    const float* ln2_g = (const float*)d_in[18];
    const float* ln2_b = (const float*)d_in[19];

    float* out = (float*)d_out;
    float* out_attn = out + (long long)BB * SS * DD;

    const int SM_G = 3 * (128 * 36 + 32 * 136) * 4;    // 107520
    const int SM_FL = (128 * 68 + 2 * 64 * 68 + 2 * 64 * 72 + 128 * 68
                       + 1024 + 512 + 512) * 4;        // 149504

    if (!g_attr_set) {
        cudaFuncSetAttribute(gemm_tc2<0, 0>,
                             cudaFuncAttributeMaxDynamicSharedMemorySize, SM_G);
        cudaFuncSetAttribute(gemm_tc2<0, 1>,
                             cudaFuncAttributeMaxDynamicSharedMemorySize, SM_G);
        cudaFuncSetAttribute(gemm_tc2<1, 1>,
                             cudaFuncAttributeMaxDynamicSharedMemorySize, SM_G);
        cudaFuncSetAttribute(flash_attn,
                             cudaFuncAttributeMaxDynamicSharedMemorySize, SM_FL);
        g_attr_set = 1;
    }

    float *pxq, *pxk, *pxv, *pw0r, *pff1r, *pff2r;
    float *pwq, *pwk, *pwv, *pq, *pk, *pv, *praw, *pconcat, *pffn1;
    cudaGetSymbolAddress((void**)&pxq, g_xq);
    cudaGetSymbolAddress((void**)&pxk, g_xk);
    cudaGetSymbolAddress((void**)&pxv, g_xv);
    cudaGetSymbolAddress((void**)&pw0r, g_w0r);
    cudaGetSymbolAddress((void**)&pff1r, g_ff1r);
    cudaGetSymbolAddress((void**)&pff2r, g_ff2r);
    cudaGetSymbolAddress((void**)&pwq, g_wq);
    cudaGetSymbolAddress((void**)&pwk, g_wk);
    cudaGetSymbolAddress((void**)&pwv, g_wv);
    cudaGetSymbolAddress((void**)&pq, g_q);
    cudaGetSymbolAddress((void**)&pk, g_k);
    cudaGetSymbolAddress((void**)&pv, g_v);
    cudaGetSymbolAddress((void**)&praw, g_att_raw);
    cudaGetSymbolAddress((void**)&pconcat, g_concat);
    cudaGetSymbolAddress((void**)&pffn1, g_ffn1);

    dim3 blk(256);
    const int MT = BB * SS;                          // 4096 token rows

    // prep: tf32-round inputs + weights
    round_copy<<<(BB * SS * DD) / 1024, blk>>>(x_q, pxq);
    round_copy<<<(BB * SS * DD) / 1024, blk>>>(x_k, pxk);
    round_copy<<<(BB * SS * DD) / 1024, blk>>>(x_v, pxv);
    round_copy<<<(DD * DD) / 1024, blk>>>(w0, pw0r);
    round_copy<<<(DD * DFF) / 1024, blk>>>(ff1_w, pff1r);
    round_copy<<<(DFF * DD) / 1024, blk>>>(ff2_w, pff2r);
    repack_kernel<<<(DD * DD) / 256, blk>>>(wq, wk, wv);

    // q/k/v projections (rounded outputs feed attention MMAs)
    gemm_tc2<0, 1><<<dim3(8, 32), blk, SM_G>>>(pxq, pwq, bq, pq, DD, DD, DD, DD);
    gemm_tc2<0, 1><<<dim3(8, 32), blk, SM_G>>>(pxk, pwk, bk, pk, DD, DD, DD, DD);
    gemm_tc2<0, 1><<<dim3(8, 32), blk, SM_G>>>(pxv, pwv, bv, pv, DD, DD, DD, DD);

    // fused attention: scores + softmax + P@V; dumps last-head raw scores
    flash_attn<<<dim3(SS / 128, BB * HH), blk, SM_FL>>>(pq, pk, pv, mask, pconcat, praw);

    // last-head attention weights -> d_out second half
    softmax_out<<<BB * SS, blk>>>(praw, out_attn);

    // mha_out = concat @ w0 + b0  (reuse g_xq)
    gemm_tc2<0, 0><<<dim3(8, 32), blk, SM_G>>>(pconcat, pw0r, b0, pxq, DD, DD, DD, DD);

    // sub1 = LN1(x_q + mha_out): exact -> g_k, rounded -> g_xk
    add_ln_kernel<<<MT, blk>>>(x_q, pxq, ln1_g, ln1_b, pk, pxk);

    // ffn1 = relu(sub1 @ ff1_w + ff1_b), rounded
    gemm_tc2<1, 1><<<dim3(32, 32), blk, SM_G>>>(pxk, pff1r, ff1_b, pffn1, DD, DD, DFF, DFF);

    // ffn2 = ffn1 @ ff2_w + ff2_b  (reuse g_xv)
    gemm_tc2<0, 0><<<dim3(8, 32), blk, SM_G>>>(pffn1, pff2r, ff2_b, pxv, DFF, DFF, DD, DD);

    // out = LN2(sub1 + ffn2) -> d_out first half
    add_ln_kernel<<<MT, blk>>>(pk, pxv, ln2_g, ln2_b, out, nullptr);
}

// round 11
// speedup vs baseline: 1.2416x; 1.2245x over previous
#include <cuda_runtime.h>
#include <math.h>
#include <stdint.h>

#define BB 4
#define SS 1024
#define DD 1024
#define HH 16
#define DK 64
#define DFF 4096

// ---------------- scratch (device globals; no allocations allowed) ----------
__device__ float g_xq[BB * SS * DD];      // rounded x_q; reused as mha_out
__device__ float g_xk[BB * SS * DD];      // rounded x_k; reused as sub1_rounded
__device__ float g_xv[BB * SS * DD];      // rounded x_v; reused as ffn2 out
__device__ float g_w0T[DD * DD];          // w0^T   [N][K], rounded
__device__ float g_ff1T[(long long)DFF * DD]; // ff1^T [4096][1024]
__device__ float g_ff2T[(long long)DD * DFF]; // ff2^T [1024][4096]
__device__ float g_wqT[DD * DD];          // qkv weights^T [n=h*64+k][d]
__device__ float g_wkT[DD * DD];
__device__ float g_wvT[DD * DD];
__device__ float g_q[BB * SS * DD];       // q [B,S,H,DK]
__device__ float g_k[BB * SS * DD];       // k; reused as sub1 (exact)
__device__ float g_v[BB * SS * DD];       // v
__device__ float g_att_raw[(long long)BB * SS * SS]; // last-head raw scores
__device__ float g_concat[BB * SS * DD];  // flash O output
__device__ float g_ffn1[(long long)BB * SS * DFF];

// ---------------- helpers ----------------------------------------------------
__device__ __forceinline__ void cp16(void* smem_dst, const float* gmem_src) {
    uint32_t s = (uint32_t)__cvta_generic_to_shared(smem_dst);
    asm volatile("cp.async.ca.shared.global [%0], [%1], 16;" :: "r"(s), "l"(gmem_src));
}
__device__ __forceinline__ void cp_commit() {
    asm volatile("cp.async.commit_group;");
}
template <int N>
__device__ __forceinline__ void cp_wait() {
    asm volatile("cp.async.wait_group %0;" :: "n"(N));
}
__device__ __forceinline__ float rna(float x) {
    uint32_t u;
    asm("cvt.rna.tf32.f32 %0, %1;" : "=r"(u) : "f"(x));
    return __uint_as_float(u);
}
__device__ __forceinline__ void mma8(float* d, const uint32_t* a, const uint32_t* b) {
    asm volatile(
        "mma.sync.aligned.m16n8k8.row.col.f32.tf32.tf32.f32 "
        "{%0,%1,%2,%3}, {%4,%5,%6,%7}, {%8,%9}, {%0,%1,%2,%3};"
        : "+f"(d[0]), "+f"(d[1]), "+f"(d[2]), "+f"(d[3])
        : "r"(a[0]), "r"(a[1]), "r"(a[2]), "r"(a[3]), "r"(b[0]), "r"(b[1]));
}
__device__ __forceinline__ uint32_t s2u(const void* p) {
    return (uint32_t)__cvta_generic_to_shared(p);
}
// ldmatrix x4 on 16-byte rows: 4 tiles of 8x4 b32 (tf32 fragment loader)
#define LDSM4(r0, r1, r2, r3, addr) \
    asm volatile("ldmatrix.sync.aligned.m8n8.x4.shared.b16 {%0,%1,%2,%3}, [%4];" \
                 : "=r"(r0), "=r"(r1), "=r"(r2), "=r"(r3) : "r"(addr))

// ---------------- prep: round-to-nearest tf32 copies -------------------------
__global__ void round_copy(const float* __restrict__ src, float* __restrict__ dst) {
    int i = blockIdx.x * 256 + threadIdx.x;
    float4 v = ((const float4*)src)[i];
    v.x = rna(v.x); v.y = rna(v.y); v.z = rna(v.z); v.w = rna(v.w);
    ((float4*)dst)[i] = v;
}

// batched transpose + round: src [z][R][C] -> dst [z][C][R]
__global__ void transT(const float* __restrict__ src, float* __restrict__ dst,
                       int R, int C) {
    __shared__ float t[32][33];
    long long zo = (long long)blockIdx.z * R * C;
    src += zo; dst += zo;
    int c0 = blockIdx.x * 32, r0 = blockIdx.y * 32;
    int x = threadIdx.x, y = threadIdx.y;   // 32 x 8
    #pragma unroll
    for (int i = 0; i < 32; i += 8)
        t[y + i][x] = src[(long long)(r0 + y + i) * C + c0 + x];
    __syncthreads();
    #pragma unroll
    for (int i = 0; i < 32; i += 8)
        dst[(long long)(c0 + y + i) * R + r0 + x] = rna(t[x][y + i]);
}

// ---------------- TF32 GEMM: R4 schedule + ldmatrix fragment loads ----------
// A [M][K] row-major, Bt [N][K] row-major (both K-contig, row stride = K).
// Block 128x128, BK=32, 8 warps (2x4), warp tile 64x32. 2-stage cp.async.
template <int RELU, int RND>
__global__ __launch_bounds__(256, 2) void gemm_lm(
    const float* __restrict__ A, const float* __restrict__ Bt,
    const float* __restrict__ bias, float* __restrict__ C,
    int K, int ldc) {
    constexpr int BM = 128, BN = 128, BK = 32, ST = 36;   // floats per row
    constexpr int STG = (BM + BN) * ST;                    // 9216 floats/stage

    extern __shared__ float sm[];                          // [2][STG]

    const int tid = threadIdx.x;
    const int lane = tid & 31, warp = tid >> 5;
    const int wrow = warp >> 2, wcol = warp & 3;
    const int row0 = blockIdx.y * BM, col0 = blockIdx.x * BN;
    const int nk = K / BK;

    auto issue = [&](int kt) {
        float* as = sm + (kt & 1) * STG;
        float* bs = as + BM * ST;
        #pragma unroll
        for (int i = 0; i < 4; i++) {
            int id = tid + 256 * i;
            int m = id >> 3, c16 = id & 7;
            cp16(as + m * ST + c16 * 4, A + (long long)(row0 + m) * K + kt * BK + c16 * 4);
        }
        #pragma unroll
        for (int i = 0; i < 4; i++) {
            int id = tid + 256 * i;
            int n = id >> 3, c16 = id & 7;
            cp16(bs + n * ST + c16 * 4, Bt + (long long)(col0 + n) * K + kt * BK + c16 * 4);
        }
        cp_commit();
    };

    float acc[4][4][4] = {};

    issue(0);
    if (nk > 1) issue(1);

    const uint32_t smu = s2u(sm);
    // ldmatrix per-lane byte offsets (tile row addresses)
    const uint32_t aoff = ((wrow * 64 + (lane & 7) + ((lane >> 3) & 1) * 8) * ST
                          + (lane >> 4) * 4) * 4;
    const uint32_t boff = ((BM * ST) + (wcol * 32 + (lane & 7) + (lane >> 4) * 8) * ST) * 4
                          + ((lane >> 3) & 1) * 16;

    for (int kt = 0; kt < nk; kt++) {
        if (kt == nk - 1) cp_wait<0>(); else cp_wait<1>();
        __syncthreads();

        const uint32_t stg = smu + (kt & 1) * STG * 4;
        #pragma unroll
        for (int ks = 0; ks < 4; ks++) {
            const uint32_t k0b = ks * 32;             // 8 floats = 32 bytes
            uint32_t af[4][4], bf[4][2];
            #pragma unroll
            for (int mt = 0; mt < 4; mt++)
                LDSM4(af[mt][0], af[mt][1], af[mt][2], af[mt][3],
                      stg + aoff + mt * (16 * ST * 4) + k0b);
            #pragma unroll
            for (int np = 0; np < 2; np++)
                LDSM4(bf[2 * np][0], bf[2 * np][1], bf[2 * np + 1][0], bf[2 * np + 1][1],
                      stg + boff + np * (16 * ST * 4) + k0b);
            #pragma unroll
            for (int mt = 0; mt < 4; mt++)
                #pragma unroll
                for (int nt = 0; nt < 4; nt++)
                    mma8(acc[mt][nt], af[mt], bf[nt]);
        }
        __syncthreads();
        if (kt + 2 < nk) issue(kt + 2);
    }

    const int r = lane >> 2, c2 = (lane & 3) * 2;
    #pragma unroll
    for (int mt = 0; mt < 4; mt++) {
        int mrow = row0 + wrow * 64 + mt * 16 + r;
        #pragma unroll
        for (int nt = 0; nt < 4; nt++) {
            int ncol = col0 + wcol * 32 + nt * 8 + c2;
            float b0 = 0.0f, b1 = 0.0f;
            if (bias) { b0 = bias[ncol]; b1 = bias[ncol + 1]; }
            float v0 = acc[mt][nt][0] + b0;
            float v1 = acc[mt][nt][1] + b1;
            float v2 = acc[mt][nt][2] + b0;
            float v3 = acc[mt][nt][3] + b1;
            if (RELU) {
                v0 = fmaxf(v0, 0.0f); v1 = fmaxf(v1, 0.0f);
                v2 = fmaxf(v2, 0.0f); v3 = fmaxf(v3, 0.0f);
            }
            if (RND) {
                v0 = rna(v0); v1 = rna(v1); v2 = rna(v2); v3 = rna(v3);
            }
            *(float2*)(C + (long long)mrow * ldc + ncol) = make_float2(v0, v1);
            *(float2*)(C + (long long)(mrow + 8) * ldc + ncol) = make_float2(v2, v3);
        }
    }
}

// ---------------- fused flash attention (proven R4 version) ------------------
__global__ __launch_bounds__(256, 1) void flash_attn(
    const float* __restrict__ Q, const float* __restrict__ K,
    const float* __restrict__ V, const float* __restrict__ mask,
    float* __restrict__ Oc, float* __restrict__ raw15) {
    constexpr int QST = 68, KST = 68, VST = 72, PST = 68;
    extern __shared__ float sm[];
    float* Qs   = sm;
    float* Ksb  = Qs + 128 * QST;
    float* Vsb  = Ksb + 2 * 64 * KST;
    float* Ps   = Vsb + 2 * 64 * VST;
    float* Msk  = Ps + 128 * PST;
    float* red0 = Msk + 1024;
    float* red1 = red0 + 512;

    const int qb = blockIdx.x, bh = blockIdx.y;
    const int b = bh >> 4, h = bh & 15;
    const float* qp = Q + ((long long)(b * SS + qb * 128)) * DD + h * 64;
    const float* kp = K + ((long long)b * SS) * DD + h * 64;
    const float* vp = V + ((long long)b * SS) * DD + h * 64;
    const float* mp = mask + b * SS;

    const int tid = threadIdx.x, lane = tid & 31, warp = tid >> 5;
    const int wrow = warp >> 2, wcol = warp & 3;
    const int r = lane >> 2, c = lane & 3;

    cp16(Msk + tid * 4, mp + tid * 4);
    #pragma unroll
    for (int i = 0; i < 8; i++) {
        int idx = tid + 256 * i;
        int m = idx >> 4, c4 = (idx & 15) * 4;
        cp16(Qs + m * QST + c4, qp + (long long)m * DD + c4);
    }
    #pragma unroll
    for (int i = 0; i < 4; i++) {
        int idx = tid + 256 * i;
        int n = idx >> 4, c4 = (idx & 15) * 4;
        cp16(Ksb + n * KST + c4, kp + (long long)n * DD + c4);
        cp16(Vsb + n * VST + c4, vp + (long long)n * DD + c4);
    }
    cp_commit();

    float acc_o[4][2][4] = {};
    float mprev[4][2], lsum[4][2];
    #pragma unroll
    for (int mt = 0; mt < 4; mt++)
        #pragma unroll
        for (int hf = 0; hf < 2; hf++) { mprev[mt][hf] = -1e30f; lsum[mt][hf] = 0.0f; }

    for (int j = 0; j < 16; j++) {
        cp_wait<0>();
        __syncthreads();
        const float* ks = Ksb + (j & 1) * 64 * KST;
        const float* vs = Vsb + (j & 1) * 64 * VST;

        float sv[4][2][4] = {};
        #pragma unroll
        for (int k0 = 0; k0 < 64; k0 += 8) {
            uint32_t af[4][4], bf[2][2];
            #pragma unroll
            for (int mt = 0; mt < 4; mt++) {
                int m = wrow * 64 + mt * 16 + r;
                af[mt][0] = *(const uint32_t*)&Qs[m * QST + k0 + c];
                af[mt][1] = *(const uint32_t*)&Qs[(m + 8) * QST + k0 + c];
                af[mt][2] = *(const uint32_t*)&Qs[m * QST + k0 + c + 4];
                af[mt][3] = *(const uint32_t*)&Qs[(m + 8) * QST + k0 + c + 4];
            }
            #pragma unroll
            for (int nt = 0; nt < 2; nt++) {
                int n = wcol * 16 + nt * 8 + r;
                bf[nt][0] = *(const uint32_t*)&ks[n * KST + k0 + c];
                bf[nt][1] = *(const uint32_t*)&ks[n * KST + k0 + c + 4];
            }
            #pragma unroll
            for (int mt = 0; mt < 4; mt++)
                #pragma unroll
                for (int nt = 0; nt < 2; nt++)
                    mma8(sv[mt][nt], af[mt], bf[nt]);
        }

        float mk[2][2];
        #pragma unroll
        for (int nt = 0; nt < 2; nt++)
            #pragma unroll
            for (int j2 = 0; j2 < 2; j2++)
                mk[nt][j2] = Msk[j * 64 + wcol * 16 + nt * 8 + 2 * c + j2] * (-1e9f);
        #pragma unroll
        for (int mt = 0; mt < 4; mt++)
            #pragma unroll
            for (int nt = 0; nt < 2; nt++)
                #pragma unroll
                for (int i = 0; i < 4; i++)
                    sv[mt][nt][i] = sv[mt][nt][i] * 0.125f + mk[nt][i & 1];

        if (h == HH - 1) {
            #pragma unroll
            for (int mt = 0; mt < 4; mt++)
                #pragma unroll
                for (int hf = 0; hf < 2; hf++) {
                    int grow = b * SS + qb * 128 + wrow * 64 + mt * 16 + r + 8 * hf;
                    #pragma unroll
                    for (int nt = 0; nt < 2; nt++) {
                        int col = j * 64 + wcol * 16 + nt * 8 + 2 * c;
                        *(float2*)(raw15 + (long long)grow * SS + col) =
                            make_float2(sv[mt][nt][2 * hf], sv[mt][nt][2 * hf + 1]);
                    }
                }
        }

        float mnew[4][2];
        #pragma unroll
        for (int mt = 0; mt < 4; mt++)
            #pragma unroll
            for (int hf = 0; hf < 2; hf++) {
                float v = fmaxf(fmaxf(sv[mt][0][2 * hf], sv[mt][0][2 * hf + 1]),
                                fmaxf(sv[mt][1][2 * hf], sv[mt][1][2 * hf + 1]));
                v = fmaxf(v, __shfl_xor_sync(0xffffffffu, v, 1));
                v = fmaxf(v, __shfl_xor_sync(0xffffffffu, v, 2));
                if (c == 0)
                    red0[(wrow * 64 + mt * 16 + r + 8 * hf) * 4 + wcol] = v;
            }
        __syncthreads();
        #pragma unroll
        for (int mt = 0; mt < 4; mt++)
            #pragma unroll
            for (int hf = 0; hf < 2; hf++) {
                int row = wrow * 64 + mt * 16 + r + 8 * hf;
                float mc = fmaxf(fmaxf(red0[row * 4 + 0], red0[row * 4 + 1]),
                                 fmaxf(red0[row * 4 + 2], red0[row * 4 + 3]));
                mnew[mt][hf] = fmaxf(mprev[mt][hf], mc);
            }

        if (j + 1 < 16) {
            float* kd = Ksb + ((j + 1) & 1) * 64 * KST;
            float* vd = Vsb + ((j + 1) & 1) * 64 * VST;
            #pragma unroll
            for (int i = 0; i < 4; i++) {
                int idx = tid + 256 * i;
                int n = idx >> 4, c4 = (idx & 15) * 4;
                cp16(kd + n * KST + c4, kp + (long long)((j + 1) * 64 + n) * DD + c4);
                cp16(vd + n * VST + c4, vp + (long long)((j + 1) * 64 + n) * DD + c4);
            }
            cp_commit();
        }

        float psum[4][2] = {};
        #pragma unroll
        for (int mt = 0; mt < 4; mt++)
            #pragma unroll
            for (int nt = 0; nt < 2; nt++)
                #pragma unroll
                for (int i = 0; i < 4; i++) {
                    float p = __expf(sv[mt][nt][i] - mnew[mt][i >> 1]);
                    sv[mt][nt][i] = p;
                    psum[mt][i >> 1] += p;
                }
        #pragma unroll
        for (int mt = 0; mt < 4; mt++)
            #pragma unroll
            for (int hf = 0; hf < 2; hf++) {
                float v = psum[mt][hf];
                v += __shfl_xor_sync(0xffffffffu, v, 1);
                v += __shfl_xor_sync(0xffffffffu, v, 2);
                if (c == 0)
                    red1[(wrow * 64 + mt * 16 + r + 8 * hf) * 4 + wcol] = v;
            }
        #pragma unroll
        for (int mt = 0; mt < 4; mt++)
            #pragma unroll
            for (int hf = 0; hf < 2; hf++) {
                int row = wrow * 64 + mt * 16 + r + 8 * hf;
                #pragma unroll
                for (int nt = 0; nt < 2; nt++) {
                    int col = wcol * 16 + nt * 8 + 2 * c;
                    *(float2*)&Ps[row * PST + col] =
                        make_float2(rna(sv[mt][nt][2 * hf]), rna(sv[mt][nt][2 * hf + 1]));
                }
            }
        __syncthreads();

        #pragma unroll
        for (int mt = 0; mt < 4; mt++)
            #pragma unroll
            for (int hf = 0; hf < 2; hf++) {
                int row = wrow * 64 + mt * 16 + r + 8 * hf;
                float sumb = red1[row * 4 + 0] + red1[row * 4 + 1] +
                             red1[row * 4 + 2] + red1[row * 4 + 3];
                float alpha = __expf(mprev[mt][hf] - mnew[mt][hf]);
                lsum[mt][hf] = lsum[mt][hf] * alpha + sumb;
                mprev[mt][hf] = mnew[mt][hf];
                #pragma unroll
                for (int nt = 0; nt < 2; nt++) {
                    acc_o[mt][nt][2 * hf] *= alpha;
                    acc_o[mt][nt][2 * hf + 1] *= alpha;
                }
            }

        #pragma unroll
        for (int k0 = 0; k0 < 64; k0 += 8) {
            uint32_t af[4][4], bf[2][2];
            #pragma unroll
            for (int mt = 0; mt < 4; mt++) {
                int m = wrow * 64 + mt * 16 + r;
                af[mt][0] = *(const uint32_t*)&Ps[m * PST + k0 + c];
                af[mt][1] = *(const uint32_t*)&Ps[(m + 8) * PST + k0 + c];
                af[mt][2] = *(const uint32_t*)&Ps[m * PST + k0 + c + 4];
                af[mt][3] = *(const uint32_t*)&Ps[(m + 8) * PST + k0 + c + 4];
            }
            #pragma unroll
            for (int nt = 0; nt < 2; nt++) {
                int n = wcol * 16 + nt * 8 + r;
                bf[nt][0] = *(const uint32_t*)&vs[(k0 + c) * VST + n];
                bf[nt][1] = *(const uint32_t*)&vs[(k0 + c + 4) * VST + n];
            }
            #pragma unroll
            for (int mt = 0; mt < 4; mt++)
                #pragma unroll
                for (int nt = 0; nt < 2; nt++)
                    mma8(acc_o[mt][nt], af[mt], bf[nt]);
        }
    }

    #pragma unroll
    for (int mt = 0; mt < 4; mt++) {
        #pragma unroll
        for (int hf = 0; hf < 2; hf++) {
            float inv = 1.0f / lsum[mt][hf];
            int grow = b * SS + qb * 128 + wrow * 64 + mt * 16 + r + 8 * hf;
            #pragma unroll
            for (int nt = 0; nt < 2; nt++) {
                int col = h * 64 + wcol * 16 + nt * 8 + 2 * c;
                *(float2*)(Oc + (long long)grow * DD + col) =
                    make_float2(rna(acc_o[mt][nt][2 * hf] * inv),
                                rna(acc_o[mt][nt][2 * hf + 1] * inv));
            }
        }
    }
}

// ---------------- softmax of dumped last-head scores -> out_attn -----------
__global__ __launch_bounds__(256) void softmax_out(
    const float* __restrict__ raw, float* __restrict__ out_attn) {
    long long rr = blockIdx.x;
    const float* row = raw + rr * SS;
    float* orow = out_attn + rr * SS;
    int tid = threadIdx.x;

    float vals[4];
    float mx = -1e30f;
    #pragma unroll
    for (int i = 0; i < 4; i++) {
        float v = row[tid + 256 * i];
        vals[i] = v;
        mx = fmaxf(mx, v);
    }
    __shared__ float red[256];
    red[tid] = mx;
    __syncthreads();
    for (int off = 128; off > 0; off >>= 1) {
        if (tid < off) red[tid] = fmaxf(red[tid], red[tid + off]);
        __syncthreads();
    }
    mx = red[0];
    __syncthreads();
    float sum = 0.0f;
    #pragma unroll
    for (int i = 0; i < 4; i++) {
        vals[i] = __expf(vals[i] - mx);
        sum += vals[i];
    }
    red[tid] = sum;
    __syncthreads();
    for (int off = 128; off > 0; off >>= 1) {
        if (tid < off) red[tid] += red[tid + off];
        __syncthreads();
    }
    float inv = 1.0f / red[0];
    #pragma unroll
    for (int i = 0; i < 4; i++)
        orow[tid + 256 * i] = vals[i] * inv;
}

// ---------------- residual add + layernorm (optional rounded copy) ---------
__global__ __launch_bounds__(256) void add_ln_kernel(
    const float* __restrict__ xa, const float* __restrict__ xb,
    const float* __restrict__ g, const float* __restrict__ bt,
    float* __restrict__ out, float* __restrict__ out_r) {
    long long rr = blockIdx.x;
    const float* pa = xa + rr * DD;
    const float* pb = xb + rr * DD;
    float* po = out + rr * DD;
    int tid = threadIdx.x;

    float v[4];
    float sum = 0.0f, sq = 0.0f;
    #pragma unroll
    for (int i = 0; i < 4; i++) {
        int cc = tid + 256 * i;
        float x = pa[cc] + pb[cc];
        v[i] = x;
        sum += x;
        sq += x * x;
    }
    __shared__ float r1[256], r2[256];
    r1[tid] = sum;
    r2[tid] = sq;
    __syncthreads();
    for (int off = 128; off > 0; off >>= 1) {
        if (tid < off) { r1[tid] += r1[tid + off]; r2[tid] += r2[tid + off]; }
        __syncthreads();
    }
    float mu = r1[0] * (1.0f / DD);
    float var = r2[0] * (1.0f / DD) - mu * mu;
    float rstd = rsqrtf(var + 1e-6f);

    #pragma unroll
    for (int i = 0; i < 4; i++) {
        int cc = tid + 256 * i;
        float y = (v[i] - mu) * rstd * g[cc] + bt[cc];
        po[cc] = y;
        if (out_r) out_r[rr * DD + cc] = rna(y);
    }
}

// ---------------- launch ----------------------------------------------------
static int g_attr_set = 0;

extern "C" void kernel_launch(void* const* d_in, const int* in_sizes, int n_in,
                              void* d_out, int out_size) {
    const float* x_v   = (const float*)d_in[0];
    const float* x_k   = (const float*)d_in[1];
    const float* x_q   = (const float*)d_in[2];
    const float* mask  = (const float*)d_in[3];
    const float* wq    = (const float*)d_in[4];
    const float* bq    = (const float*)d_in[5];
    const float* wk    = (const float*)d_in[6];
    const float* bk    = (const float*)d_in[7];
    const float* wv    = (const float*)d_in[8];
    const float* bv    = (const float*)d_in[9];
    const float* w0    = (const float*)d_in[10];
    const float* b0    = (const float*)d_in[11];
    const float* ln1_g = (const float*)d_in[12];
    const float* ln1_b = (const float*)d_in[13];
    const float* ff1_w = (const float*)d_in[14];
    const float* ff1_b = (const float*)d_in[15];
    const float* ff2_w = (const float*)d_in[16];
    const float* ff2_b = (const float*)d_in[17];
    const float* ln2_g = (const float*)d_in[18];
    const float* ln2_b = (const float*)d_in[19];

    float* out = (float*)d_out;
    float* out_attn = out + (long long)BB * SS * DD;

    const int SM_G = 2 * (128 * 36 + 128 * 36) * 4;        // 73728
    const int SM_FL = (128 * 68 + 2 * 64 * 68 + 2 * 64 * 72 + 128 * 68
                       + 1024 + 512 + 512) * 4;            // 149504

    if (!g_attr_set) {
        cudaFuncSetAttribute(gemm_lm<0, 0>,
                             cudaFuncAttributeMaxDynamicSharedMemorySize, SM_G);
        cudaFuncSetAttribute(gemm_lm<0, 1>,
                             cudaFuncAttributeMaxDynamicSharedMemorySize, SM_G);
        cudaFuncSetAttribute(gemm_lm<1, 1>,
                             cudaFuncAttributeMaxDynamicSharedMemorySize, SM_G);
        cudaFuncSetAttribute(flash_attn,
                             cudaFuncAttributeMaxDynamicSharedMemorySize, SM_FL);
        g_attr_set = 1;
    }

    float *pxq, *pxk, *pxv, *pw0T, *pff1T, *pff2T;
    float *pwqT, *pwkT, *pwvT, *pq, *pk, *pv, *praw, *pconcat, *pffn1;
    cudaGetSymbolAddress((void**)&pxq, g_xq);
    cudaGetSymbolAddress((void**)&pxk, g_xk);
    cudaGetSymbolAddress((void**)&pxv, g_xv);
    cudaGetSymbolAddress((void**)&pw0T, g_w0T);
    cudaGetSymbolAddress((void**)&pff1T, g_ff1T);
    cudaGetSymbolAddress((void**)&pff2T, g_ff2T);
    cudaGetSymbolAddress((void**)&pwqT, g_wqT);
    cudaGetSymbolAddress((void**)&pwkT, g_wkT);
    cudaGetSymbolAddress((void**)&pwvT, g_wvT);
    cudaGetSymbolAddress((void**)&pq, g_q);
    cudaGetSymbolAddress((void**)&pk, g_k);
    cudaGetSymbolAddress((void**)&pv, g_v);
    cudaGetSymbolAddress((void**)&praw, g_att_raw);
    cudaGetSymbolAddress((void**)&pconcat, g_concat);
    cudaGetSymbolAddress((void**)&pffn1, g_ffn1);

    dim3 blk(256);
    dim3 tblk(32, 8);
    const int MT = BB * SS;

    // prep: round inputs; transpose+round all GEMM B operands to [N][K]
    round_copy<<<(BB * SS * DD) / 1024, blk>>>(x_q, pxq);
    round_copy<<<(BB * SS * DD) / 1024, blk>>>(x_k, pxk);
    round_copy<<<(BB * SS * DD) / 1024, blk>>>(x_v, pxv);
    transT<<<dim3(2, 32, HH), tblk>>>(wq, pwqT, DD, DK);   // [h][d][k]->[h*64+k][d]
    transT<<<dim3(2, 32, HH), tblk>>>(wk, pwkT, DD, DK);
    transT<<<dim3(2, 32, HH), tblk>>>(wv, pwvT, DD, DK);
    transT<<<dim3(32, 32, 1), tblk>>>(w0, pw0T, DD, DD);
    transT<<<dim3(128, 32, 1), tblk>>>(ff1_w, pff1T, DD, DFF);
    transT<<<dim3(32, 128, 1), tblk>>>(ff2_w, pff2T, DFF, DD);

    // q/k/v projections (rounded outputs feed attention MMAs)
    gemm_lm<0, 1><<<dim3(8, 32), blk, SM_G>>>(pxq, pwqT, bq, pq, DD, DD);
    gemm_lm<0, 1><<<dim3(8, 32), blk, SM_G>>>(pxk, pwkT, bk, pk, DD, DD);
    gemm_lm<0, 1><<<dim3(8, 32), blk, SM_G>>>(pxv, pwvT, bv, pv, DD, DD);

    // fused attention: scores + softmax + P@V; dumps last-head raw scores
    flash_attn<<<dim3(SS / 128, BB * HH), blk, SM_FL>>>(pq, pk, pv, mask, pconcat, praw);

    // last-head attention weights -> d_out second half
    softmax_out<<<BB * SS, blk>>>(praw, out_attn);

    // mha_out = concat @ w0 + b0  (reuse g_xq)
    gemm_lm<0, 0><<<dim3(8, 32), blk, SM_G>>>(pconcat, pw0T, b0, pxq, DD, DD);

    // sub1 = LN1(x_q + mha_out): exact -> g_k, rounded -> g_xk
    add_ln_kernel<<<MT, blk>>>(x_q, pxq, ln1_g, ln1_b, pk, pxk);

    // ffn1 = relu(sub1 @ ff1_w + ff1_b), rounded
    gemm_lm<1, 1><<<dim3(32, 32), blk, SM_G>>>(pxk, pff1T, ff1_b, pffn1, DD, DFF);

    // ffn2 = ffn1 @ ff2_w + ff2_b  (reuse g_xv)
    gemm_lm<0, 0><<<dim3(8, 32), blk, SM_G>>>(pffn1, pff2T, ff2_b, pxv, DFF, DD);

    // out = LN2(sub1 + ffn2) -> d_out first half
    add_ln_kernel<<<MT, blk>>>(pk, pxv, ln2_g, ln2_b, out, nullptr);
}

// round 12
// speedup vs baseline: 1.2544x; 1.0103x over previous
#include <cuda_runtime.h>
#include <math.h>
#include <stdint.h>

#define BB 4
#define SS 1024
#define DD 1024
#define HH 16
#define DK 64
#define DFF 4096
#define PL (BB * SS * DD)      // plane stride for x/qkv cat buffers
#define WPL (DD * DD)          // plane stride for qkv weightsT

// ---------------- scratch (device globals; no allocations allowed) ----------
__device__ float g_xcat[3 * BB * SS * DD]; // rounded xq/xk/xv; planes reused:
                                           // 0 = mha_out, 1 = sub1_rounded, 2 = ffn2 out
__device__ float g_qkv[3 * BB * SS * DD];  // q/k/v planes [B,S,H,DK]
__device__ float g_wqkvT[3 * DD * DD];     // qkv weightsT planes [n=h*64+k][d]
__device__ float g_bqkv[3 * DD];           // concat bias
__device__ float g_w0T[DD * DD];
__device__ float g_ff1T[(long long)DFF * DD];
__device__ float g_ff2T[(long long)DD * DFF];
__device__ float g_k[BB * SS * DD];        // sub1 (exact)
__device__ float g_att_raw[(long long)BB * SS * SS]; // last-head raw scores
__device__ float g_concat[BB * SS * DD];   // flash O output
__device__ float g_ffn1[(long long)BB * SS * DFF];

// ---------------- helpers ----------------------------------------------------
__device__ __forceinline__ void cp16(void* smem_dst, const float* gmem_src) {
    uint32_t s = (uint32_t)__cvta_generic_to_shared(smem_dst);
    asm volatile("cp.async.ca.shared.global [%0], [%1], 16;" :: "r"(s), "l"(gmem_src));
}
__device__ __forceinline__ void cp_commit() {
    asm volatile("cp.async.commit_group;");
}
template <int N>
__device__ __forceinline__ void cp_wait() {
    asm volatile("cp.async.wait_group %0;" :: "n"(N));
}
__device__ __forceinline__ float rna(float x) {
    uint32_t u;
    asm("cvt.rna.tf32.f32 %0, %1;" : "=r"(u) : "f"(x));
    return __uint_as_float(u);
}
__device__ __forceinline__ void mma8(float* d, const uint32_t* a, const uint32_t* b) {
    asm volatile(
        "mma.sync.aligned.m16n8k8.row.col.f32.tf32.tf32.f32 "
        "{%0,%1,%2,%3}, {%4,%5,%6,%7}, {%8,%9}, {%0,%1,%2,%3};"
        : "+f"(d[0]), "+f"(d[1]), "+f"(d[2]), "+f"(d[3])
        : "r"(a[0]), "r"(a[1]), "r"(a[2]), "r"(a[3]), "r"(b[0]), "r"(b[1]));
}
__device__ __forceinline__ uint32_t s2u(const void* p) {
    return (uint32_t)__cvta_generic_to_shared(p);
}
// ldmatrix x4 on 16-byte rows: 4 tiles of 8x4 b32 (tf32 fragment loader)
#define LDSM4(r0, r1, r2, r3, addr) \
    asm volatile("ldmatrix.sync.aligned.m8n8.x4.shared.b16 {%0,%1,%2,%3}, [%4];" \
                 : "=r"(r0), "=r"(r1), "=r"(r2), "=r"(r3) : "r"(addr))

// ---------------- prep kernels -----------------------------------------------
__global__ void round_copy(const float* __restrict__ src, float* __restrict__ dst) {
    int i = blockIdx.x * 256 + threadIdx.x;
    float4 v = ((const float4*)src)[i];
    v.x = rna(v.x); v.y = rna(v.y); v.z = rna(v.z); v.w = rna(v.w);
    ((float4*)dst)[i] = v;
}

__global__ void concat_bias(const float* __restrict__ bq, const float* __restrict__ bk,
                            const float* __restrict__ bv, float* __restrict__ dst) {
    int i = blockIdx.x * 256 + threadIdx.x;   // 0..3071
    dst[i] = i < 1024 ? bq[i] : (i < 2048 ? bk[i - 1024] : bv[i - 2048]);
}

// batched transpose + round: src [z][R][C] -> dst [z][C][R]
__global__ void transT(const float* __restrict__ src, float* __restrict__ dst,
                       int R, int C) {
    __shared__ float t[32][33];
    long long zo = (long long)blockIdx.z * R * C;
    src += zo; dst += zo;
    int c0 = blockIdx.x * 32, r0 = blockIdx.y * 32;
    int x = threadIdx.x, y = threadIdx.y;   // 32 x 8
    #pragma unroll
    for (int i = 0; i < 32; i += 8)
        t[y + i][x] = src[(long long)(r0 + y + i) * C + c0 + x];
    __syncthreads();
    #pragma unroll
    for (int i = 0; i < 32; i += 8)
        dst[(long long)(c0 + y + i) * R + r0 + x] = rna(t[x][y + i]);
}

// ---------------- TF32 GEMM: ldmatrix fragments, optional z-batching --------
// A [M][K] row-major, Bt [N][K] row-major. Block 128x128, BK=32,
// 8 warps (2x4), warp tile 64x32, 2-stage cp.async. z strides for batching.
template <int RELU, int RND>
__global__ __launch_bounds__(256, 2) void gemm_lm(
    const float* __restrict__ A, const float* __restrict__ Bt,
    const float* __restrict__ bias, float* __restrict__ C,
    int K, int ldc,
    long long sA, long long sB, long long sBias, long long sC) {
    constexpr int BM = 128, BN = 128, BK = 32, ST = 36;
    constexpr int STG = (BM + BN) * ST;

    extern __shared__ float sm[];

    const int z = blockIdx.z;
    A += (long long)z * sA;
    Bt += (long long)z * sB;
    if (bias) bias += (long long)z * sBias;
    C += (long long)z * sC;

    const int tid = threadIdx.x;
    const int lane = tid & 31, warp = tid >> 5;
    const int wrow = warp >> 2, wcol = warp & 3;
    const int row0 = blockIdx.y * BM, col0 = blockIdx.x * BN;
    const int nk = K / BK;

    auto issue = [&](int kt) {
        float* as = sm + (kt & 1) * STG;
        float* bs = as + BM * ST;
        #pragma unroll
        for (int i = 0; i < 4; i++) {
            int id = tid + 256 * i;
            int m = id >> 3, c16 = id & 7;
            cp16(as + m * ST + c16 * 4, A + (long long)(row0 + m) * K + kt * BK + c16 * 4);
        }
        #pragma unroll
        for (int i = 0; i < 4; i++) {
            int id = tid + 256 * i;
            int n = id >> 3, c16 = id & 7;
            cp16(bs + n * ST + c16 * 4, Bt + (long long)(col0 + n) * K + kt * BK + c16 * 4);
        }
        cp_commit();
    };

    float acc[4][4][4] = {};

    issue(0);
    if (nk > 1) issue(1);

    const uint32_t smu = s2u(sm);
    const uint32_t aoff = ((wrow * 64 + (lane & 7) + ((lane >> 3) & 1) * 8) * ST
                          + (lane >> 4) * 4) * 4;
    const uint32_t boff = ((BM * ST) + (wcol * 32 + (lane & 7) + (lane >> 4) * 8) * ST) * 4
                          + ((lane >> 3) & 1) * 16;

    for (int kt = 0; kt < nk; kt++) {
        if (kt == nk - 1) cp_wait<0>(); else cp_wait<1>();
        __syncthreads();

        const uint32_t stg = smu + (kt & 1) * STG * 4;
        #pragma unroll
        for (int ks = 0; ks < 4; ks++) {
            const uint32_t k0b = ks * 32;
            uint32_t af[4][4], bf[4][2];
            #pragma unroll
            for (int mt = 0; mt < 4; mt++)
                LDSM4(af[mt][0], af[mt][1], af[mt][2], af[mt][3],
                      stg + aoff + mt * (16 * ST * 4) + k0b);
            #pragma unroll
            for (int np = 0; np < 2; np++)
                LDSM4(bf[2 * np][0], bf[2 * np][1], bf[2 * np + 1][0], bf[2 * np + 1][1],
                      stg + boff + np * (16 * ST * 4) + k0b);
            #pragma unroll
            for (int mt = 0; mt < 4; mt++)
                #pragma unroll
                for (int nt = 0; nt < 4; nt++)
                    mma8(acc[mt][nt], af[mt], bf[nt]);
        }
        __syncthreads();
        if (kt + 2 < nk) issue(kt + 2);
    }

    const int r = lane >> 2, c2 = (lane & 3) * 2;
    #pragma unroll
    for (int mt = 0; mt < 4; mt++) {
        int mrow = row0 + wrow * 64 + mt * 16 + r;
        #pragma unroll
        for (int nt = 0; nt < 4; nt++) {
            int ncol = col0 + wcol * 32 + nt * 8 + c2;
            float b0 = 0.0f, b1 = 0.0f;
            if (bias) { b0 = bias[ncol]; b1 = bias[ncol + 1]; }
            float v0 = acc[mt][nt][0] + b0;
            float v1 = acc[mt][nt][1] + b1;
            float v2 = acc[mt][nt][2] + b0;
            float v3 = acc[mt][nt][3] + b1;
            if (RELU) {
                v0 = fmaxf(v0, 0.0f); v1 = fmaxf(v1, 0.0f);
                v2 = fmaxf(v2, 0.0f); v3 = fmaxf(v3, 0.0f);
            }
            if (RND) {
                v0 = rna(v0); v1 = rna(v1); v2 = rna(v2); v3 = rna(v3);
            }
            *(float2*)(C + (long long)mrow * ldc + ncol) = make_float2(v0, v1);
            *(float2*)(C + (long long)(mrow + 8) * ldc + ncol) = make_float2(v2, v3);
        }
    }
}

// ---------------- fused flash attention (ldmatrix fragment loads) ------------
// grid (S/128, B*H). QKV planes: q at +0, k at +PL, v at +2*PL.
__global__ __launch_bounds__(256, 1) void flash_attn(
    const float* __restrict__ QKV, const float* __restrict__ mask,
    float* __restrict__ Oc, float* __restrict__ raw15) {
    constexpr int QST = 68, KST = 68, VST = 72, PST = 68;
    extern __shared__ float sm[];
    float* Qs   = sm;
    float* Ksb  = Qs + 128 * QST;
    float* Vsb  = Ksb + 2 * 64 * KST;
    float* Ps   = Vsb + 2 * 64 * VST;
    float* Msk  = Ps + 128 * PST;
    float* red0 = Msk + 1024;
    float* red1 = red0 + 512;

    const int qb = blockIdx.x, bh = blockIdx.y;
    const int b = bh >> 4, h = bh & 15;
    const float* qp = QKV + ((long long)(b * SS + qb * 128)) * DD + h * 64;
    const float* kp = QKV + PL + ((long long)b * SS) * DD + h * 64;
    const float* vp = QKV + 2 * PL + ((long long)b * SS) * DD + h * 64;
    const float* mp = mask + b * SS;

    const int tid = threadIdx.x, lane = tid & 31, warp = tid >> 5;
    const int wrow = warp >> 2, wcol = warp & 3;
    const int r = lane >> 2, c = lane & 3;

    cp16(Msk + tid * 4, mp + tid * 4);
    #pragma unroll
    for (int i = 0; i < 8; i++) {
        int idx = tid + 256 * i;
        int m = idx >> 4, c4 = (idx & 15) * 4;
        cp16(Qs + m * QST + c4, qp + (long long)m * DD + c4);
    }
    #pragma unroll
    for (int i = 0; i < 4; i++) {
        int idx = tid + 256 * i;
        int n = idx >> 4, c4 = (idx & 15) * 4;
        cp16(Ksb + n * KST + c4, kp + (long long)n * DD + c4);
        cp16(Vsb + n * VST + c4, vp + (long long)n * DD + c4);
    }
    cp_commit();

    // ldmatrix per-lane byte offsets
    const uint32_t qs_u = s2u(Qs), ks0_u = s2u(Ksb), ps_u = s2u(Ps);
    const uint32_t aoffQ = ((wrow * 64 + (lane & 7) + ((lane >> 3) & 1) * 8) * QST
                           + (lane >> 4) * 4) * 4;
    const uint32_t boffK = ((wcol * 16 + (lane & 7) + (lane >> 4) * 8) * KST) * 4
                           + ((lane >> 3) & 1) * 16;
    const uint32_t aoffP = ((wrow * 64 + (lane & 7) + ((lane >> 3) & 1) * 8) * PST
                           + (lane >> 4) * 4) * 4;

    float acc_o[4][2][4] = {};
    float mprev[4][2], lsum[4][2];
    #pragma unroll
    for (int mt = 0; mt < 4; mt++)
        #pragma unroll
        for (int hf = 0; hf < 2; hf++) { mprev[mt][hf] = -1e30f; lsum[mt][hf] = 0.0f; }

    for (int j = 0; j < 16; j++) {
        cp_wait<0>();
        __syncthreads();
        const uint32_t ks_u = ks0_u + (j & 1) * 64 * KST * 4;
        const float* vs = Vsb + (j & 1) * 64 * VST;

        // S = Q @ K^T  (ldmatrix fragments)
        float sv[4][2][4] = {};
        #pragma unroll
        for (int k0 = 0; k0 < 64; k0 += 8) {
            uint32_t af[4][4], bf[2][2];
            #pragma unroll
            for (int mt = 0; mt < 4; mt++)
                LDSM4(af[mt][0], af[mt][1], af[mt][2], af[mt][3],
                      qs_u + aoffQ + mt * (16 * QST * 4) + k0 * 4);
            LDSM4(bf[0][0], bf[0][1], bf[1][0], bf[1][1],
                  ks_u + boffK + k0 * 4);
            #pragma unroll
            for (int mt = 0; mt < 4; mt++)
                #pragma unroll
                for (int nt = 0; nt < 2; nt++)
                    mma8(sv[mt][nt], af[mt], bf[nt]);
        }

        float mk[2][2];
        #pragma unroll
        for (int nt = 0; nt < 2; nt++)
            #pragma unroll
            for (int j2 = 0; j2 < 2; j2++)
                mk[nt][j2] = Msk[j * 64 + wcol * 16 + nt * 8 + 2 * c + j2] * (-1e9f);
        #pragma unroll
        for (int mt = 0; mt < 4; mt++)
            #pragma unroll
            for (int nt = 0; nt < 2; nt++)
                #pragma unroll
                for (int i = 0; i < 4; i++)
                    sv[mt][nt][i] = sv[mt][nt][i] * 0.125f + mk[nt][i & 1];

        if (h == HH - 1) {
            #pragma unroll
            for (int mt = 0; mt < 4; mt++)
                #pragma unroll
                for (int hf = 0; hf < 2; hf++) {
                    int grow = b * SS + qb * 128 + wrow * 64 + mt * 16 + r + 8 * hf;
                    #pragma unroll
                    for (int nt = 0; nt < 2; nt++) {
                        int col = j * 64 + wcol * 16 + nt * 8 + 2 * c;
                        *(float2*)(raw15 + (long long)grow * SS + col) =
                            make_float2(sv[mt][nt][2 * hf], sv[mt][nt][2 * hf + 1]);
                    }
                }
        }

        float mnew[4][2];
        #pragma unroll
        for (int mt = 0; mt < 4; mt++)
            #pragma unroll
            for (int hf = 0; hf < 2; hf++) {
                float v = fmaxf(fmaxf(sv[mt][0][2 * hf], sv[mt][0][2 * hf + 1]),
                                fmaxf(sv[mt][1][2 * hf], sv[mt][1][2 * hf + 1]));
                v = fmaxf(v, __shfl_xor_sync(0xffffffffu, v, 1));
                v = fmaxf(v, __shfl_xor_sync(0xffffffffu, v, 2));
                if (c == 0)
                    red0[(wrow * 64 + mt * 16 + r + 8 * hf) * 4 + wcol] = v;
            }
        __syncthreads();
        #pragma unroll
        for (int mt = 0; mt < 4; mt++)
            #pragma unroll
            for (int hf = 0; hf < 2; hf++) {
                int row = wrow * 64 + mt * 16 + r + 8 * hf;
                float mc = fmaxf(fmaxf(red0[row * 4 + 0], red0[row * 4 + 1]),
                                 fmaxf(red0[row * 4 + 2], red0[row * 4 + 3]));
                mnew[mt][hf] = fmaxf(mprev[mt][hf], mc);
            }

        if (j + 1 < 16) {
            float* kd = Ksb + ((j + 1) & 1) * 64 * KST;
            float* vd = Vsb + ((j + 1) & 1) * 64 * VST;
            #pragma unroll
            for (int i = 0; i < 4; i++) {
                int idx = tid + 256 * i;
                int n = idx >> 4, c4 = (idx & 15) * 4;
                cp16(kd + n * KST + c4, kp + (long long)((j + 1) * 64 + n) * DD + c4);
                cp16(vd + n * VST + c4, vp + (long long)((j + 1) * 64 + n) * DD + c4);
            }
            cp_commit();
        }

        float psum[4][2] = {};
        #pragma unroll
        for (int mt = 0; mt < 4; mt++)
            #pragma unroll
            for (int nt = 0; nt < 2; nt++)
                #pragma unroll
                for (int i = 0; i < 4; i++) {
                    float p = __expf(sv[mt][nt][i] - mnew[mt][i >> 1]);
                    sv[mt][nt][i] = p;
                    psum[mt][i >> 1] += p;
                }
        #pragma unroll
        for (int mt = 0; mt < 4; mt++)
            #pragma unroll
            for (int hf = 0; hf < 2; hf++) {
                float v = psum[mt][hf];
                v += __shfl_xor_sync(0xffffffffu, v, 1);
                v += __shfl_xor_sync(0xffffffffu, v, 2);
                if (c == 0)
                    red1[(wrow * 64 + mt * 16 + r + 8 * hf) * 4 + wcol] = v;
            }
        #pragma unroll
        for (int mt = 0; mt < 4; mt++)
            #pragma unroll
            for (int hf = 0; hf < 2; hf++) {
                int row = wrow * 64 + mt * 16 + r + 8 * hf;
                #pragma unroll
                for (int nt = 0; nt < 2; nt++) {
                    int col = wcol * 16 + nt * 8 + 2 * c;
                    *(float2*)&Ps[row * PST + col] =
                        make_float2(rna(sv[mt][nt][2 * hf]), rna(sv[mt][nt][2 * hf + 1]));
                }
            }
        __syncthreads();

        #pragma unroll
        for (int mt = 0; mt < 4; mt++)
            #pragma unroll
            for (int hf = 0; hf < 2; hf++) {
                int row = wrow * 64 + mt * 16 + r + 8 * hf;
                float sumb = red1[row * 4 + 0] + red1[row * 4 + 1] +
                             red1[row * 4 + 2] + red1[row * 4 + 3];
                float alpha = __expf(mprev[mt][hf] - mnew[mt][hf]);
                lsum[mt][hf] = lsum[mt][hf] * alpha + sumb;
                mprev[mt][hf] = mnew[mt][hf];
                #pragma unroll
                for (int nt = 0; nt < 2; nt++) {
                    acc_o[mt][nt][2 * hf] *= alpha;
                    acc_o[mt][nt][2 * hf + 1] *= alpha;
                }
            }

        // O += P @ V (A-side ldmatrix; V-side scalar, [k][n] layout)
        #pragma unroll
        for (int k0 = 0; k0 < 64; k0 += 8) {
            uint32_t af[4][4], bf[2][2];
            #pragma unroll
            for (int mt = 0; mt < 4; mt++)
                LDSM4(af[mt][0], af[mt][1], af[mt][2], af[mt][3],
                      ps_u + aoffP + mt * (16 * PST * 4) + k0 * 4);
            #pragma unroll
            for (int nt = 0; nt < 2; nt++) {
                int n = wcol * 16 + nt * 8 + r;
                bf[nt][0] = *(const uint32_t*)&vs[(k0 + c) * VST + n];
                bf[nt][1] = *(const uint32_t*)&vs[(k0 + c + 4) * VST + n];
            }
            #pragma unroll
            for (int mt = 0; mt < 4; mt++)
                #pragma unroll
                for (int nt = 0; nt < 2; nt++)
                    mma8(acc_o[mt][nt], af[mt], bf[nt]);
        }
    }

    #pragma unroll
    for (int mt = 0; mt < 4; mt++) {
        #pragma unroll
        for (int hf = 0; hf < 2; hf++) {
            float inv = 1.0f / lsum[mt][hf];
            int grow = b * SS + qb * 128 + wrow * 64 + mt * 16 + r + 8 * hf;
            #pragma unroll
            for (int nt = 0; nt < 2; nt++) {
                int col = h * 64 + wcol * 16 + nt * 8 + 2 * c;
                *(float2*)(Oc + (long long)grow * DD + col) =
                    make_float2(rna(acc_o[mt][nt][2 * hf] * inv),
                                rna(acc_o[mt][nt][2 * hf + 1] * inv));
            }
        }
    }
}

// ---------------- softmax of dumped last-head scores -> out_attn -----------
__global__ __launch_bounds__(256) void softmax_out(
    const float* __restrict__ raw, float* __restrict__ out_attn) {
    long long rr = blockIdx.x;
    const float* row = raw + rr * SS;
    float* orow = out_attn + rr * SS;
    int tid = threadIdx.x;

    float vals[4];
    float mx = -1e30f;
    #pragma unroll
    for (int i = 0; i < 4; i++) {
        float v = row[tid + 256 * i];
        vals[i] = v;
        mx = fmaxf(mx, v);
    }
    __shared__ float red[256];
    red[tid] = mx;
    __syncthreads();
    for (int off = 128; off > 0; off >>= 1) {
        if (tid < off) red[tid] = fmaxf(red[tid], red[tid + off]);
        __syncthreads();
    }
    mx = red[0];
    __syncthreads();
    float sum = 0.0f;
    #pragma unroll
    for (int i = 0; i < 4; i++) {
        vals[i] = __expf(vals[i] - mx);
        sum += vals[i];
    }
    red[tid] = sum;
    __syncthreads();
    for (int off = 128; off > 0; off >>= 1) {
        if (tid < off) red[tid] += red[tid + off];
        __syncthreads();
    }
    float inv = 1.0f / red[0];
    #pragma unroll
    for (int i = 0; i < 4; i++)
        orow[tid + 256 * i] = vals[i] * inv;
}

// ---------------- residual add + layernorm (optional rounded copy) ---------
__global__ __launch_bounds__(256) void add_ln_kernel(
    const float* __restrict__ xa, const float* __restrict__ xb,
    const float* __restrict__ g, const float* __restrict__ bt,
    float* __restrict__ out, float* __restrict__ out_r) {
    long long rr = blockIdx.x;
    const float* pa = xa + rr * DD;
    const float* pb = xb + rr * DD;
    float* po = out + rr * DD;
    int tid = threadIdx.x;

    float v[4];
    float sum = 0.0f, sq = 0.0f;
    #pragma unroll
    for (int i = 0; i < 4; i++) {
        int cc = tid + 256 * i;
        float x = pa[cc] + pb[cc];
        v[i] = x;
        sum += x;
        sq += x * x;
    }
    __shared__ float r1[256], r2[256];
    r1[tid] = sum;
    r2[tid] = sq;
    __syncthreads();
    for (int off = 128; off > 0; off >>= 1) {
        if (tid < off) { r1[tid] += r1[tid + off]; r2[tid] += r2[tid + off]; }
        __syncthreads();
    }
    float mu = r1[0] * (1.0f / DD);
    float var = r2[0] * (1.0f / DD) - mu * mu;
    float rstd = rsqrtf(var + 1e-6f);

    #pragma unroll
    for (int i = 0; i < 4; i++) {
        int cc = tid + 256 * i;
        float y = (v[i] - mu) * rstd * g[cc] + bt[cc];
        po[cc] = y;
        if (out_r) out_r[rr * DD + cc] = rna(y);
    }
}

// ---------------- launch ----------------------------------------------------
static int g_attr_set = 0;

extern "C" void kernel_launch(void* const* d_in, const int* in_sizes, int n_in,
                              void* d_out, int out_size) {
    const float* x_v   = (const float*)d_in[0];
    const float* x_k   = (const float*)d_in[1];
    const float* x_q   = (const float*)d_in[2];
    const float* mask  = (const float*)d_in[3];
    const float* wq    = (const float*)d_in[4];
    const float* bq    = (const float*)d_in[5];
    const float* wk    = (const float*)d_in[6];
    const float* bk    = (const float*)d_in[7];
    const float* wv    = (const float*)d_in[8];
    const float* bv    = (const float*)d_in[9];
    const float* w0    = (const float*)d_in[10];
    const float* b0    = (const float*)d_in[11];
    const float* ln1_g = (const float*)d_in[12];
    const float* ln1_b = (const float*)d_in[13];
    const float* ff1_w = (const float*)d_in[14];
    const float* ff1_b = (const float*)d_in[15];
    const float* ff2_w = (const float*)d_in[16];
    const float* ff2_b = (const float*)d_in[17];
    const float* ln2_g = (const float*)d_in[18];
    const float* ln2_b = (const float*)d_in[19];

    float* out = (float*)d_out;
    float* out_attn = out + (long long)BB * SS * DD;

    const int SM_G = 2 * (128 * 36 + 128 * 36) * 4;        // 73728
    const int SM_FL = (128 * 68 + 2 * 64 * 68 + 2 * 64 * 72 + 128 * 68
                       + 1024 + 512 + 512) * 4;            // 149504

    if (!g_attr_set) {
        cudaFuncSetAttribute(gemm_lm<0, 0>,
                             cudaFuncAttributeMaxDynamicSharedMemorySize, SM_G);
        cudaFuncSetAttribute(gemm_lm<0, 1>,
                             cudaFuncAttributeMaxDynamicSharedMemorySize, SM_G);
        cudaFuncSetAttribute(gemm_lm<1, 1>,
                             cudaFuncAttributeMaxDynamicSharedMemorySize, SM_G);
        cudaFuncSetAttribute(flash_attn,
                             cudaFuncAttributeMaxDynamicSharedMemorySize, SM_FL);
        g_attr_set = 1;
    }

    float *pxcat, *pqkv, *pwT, *pbqkv, *pw0T, *pff1T, *pff2T;
    float *pk, *praw, *pconcat, *pffn1;
    cudaGetSymbolAddress((void**)&pxcat, g_xcat);
    cudaGetSymbolAddress((void**)&pqkv, g_qkv);
    cudaGetSymbolAddress((void**)&pwT, g_wqkvT);
    cudaGetSymbolAddress((void**)&pbqkv, g_bqkv);
    cudaGetSymbolAddress((void**)&pw0T, g_w0T);
    cudaGetSymbolAddress((void**)&pff1T, g_ff1T);
    cudaGetSymbolAddress((void**)&pff2T, g_ff2T);
    cudaGetSymbolAddress((void**)&pk, g_k);
    cudaGetSymbolAddress((void**)&praw, g_att_raw);
    cudaGetSymbolAddress((void**)&pconcat, g_concat);
    cudaGetSymbolAddress((void**)&pffn1, g_ffn1);

    dim3 blk(256);
    dim3 tblk(32, 8);
    const int MT = BB * SS;

    // prep: round inputs into cat planes; transpose+round weights; concat bias
    round_copy<<<PL / 1024, blk>>>(x_q, pxcat);
    round_copy<<<PL / 1024, blk>>>(x_k, pxcat + PL);
    round_copy<<<PL / 1024, blk>>>(x_v, pxcat + 2 * PL);
    transT<<<dim3(2, 32, HH), tblk>>>(wq, pwT, DD, DK);
    transT<<<dim3(2, 32, HH), tblk>>>(wk, pwT + WPL, DD, DK);
    transT<<<dim3(2, 32, HH), tblk>>>(wv, pwT + 2 * WPL, DD, DK);
    transT<<<dim3(32, 32, 1), tblk>>>(w0, pw0T, DD, DD);
    transT<<<dim3(128, 32, 1), tblk>>>(ff1_w, pff1T, DD, DFF);
    transT<<<dim3(32, 128, 1), tblk>>>(ff2_w, pff2T, DFF, DD);
    concat_bias<<<12, blk>>>(bq, bk, bv, pbqkv);

    // q/k/v projections: one z-batched launch (768 CTAs)
    gemm_lm<0, 1><<<dim3(8, 32, 3), blk, SM_G>>>(pxcat, pwT, pbqkv, pqkv,
        DD, DD, PL, WPL, DD, PL);

    // fused attention: scores + softmax + P@V; dumps last-head raw scores
    flash_attn<<<dim3(SS / 128, BB * HH), blk, SM_FL>>>(pqkv, mask, pconcat, praw);

    // last-head attention weights -> d_out second half
    softmax_out<<<BB * SS, blk>>>(praw, out_attn);

    // mha_out = concat @ w0 + b0  (into g_xcat plane 0)
    gemm_lm<0, 0><<<dim3(8, 32, 1), blk, SM_G>>>(pconcat, pw0T, b0, pxcat,
        DD, DD, 0, 0, 0, 0);

    // sub1 = LN1(x_q + mha_out): exact -> g_k, rounded -> g_xcat plane 1
    add_ln_kernel<<<MT, blk>>>(x_q, pxcat, ln1_g, ln1_b, pk, pxcat + PL);

    // ffn1 = relu(sub1 @ ff1_w + ff1_b), rounded
    gemm_lm<1, 1><<<dim3(32, 32, 1), blk, SM_G>>>(pxcat + PL, pff1T, ff1_b, pffn1,
        DD, DFF, 0, 0, 0, 0);

    // ffn2 = ffn1 @ ff2_w + ff2_b  (into g_xcat plane 2)
    gemm_lm<0, 0><<<dim3(8, 32, 1), blk, SM_G>>>(pffn1, pff2T, ff2_b, pxcat + 2 * PL,
        DFF, DD, 0, 0, 0, 0);

    // out = LN2(sub1 + ffn2) -> d_out first half
    add_ln_kernel<<<MT, blk>>>(pk, pxcat + 2 * PL, ln2_g, ln2_b, out, nullptr);
}

// round 13
// speedup vs baseline: 1.8702x; 1.4909x over previous
#include <cuda_runtime.h>
#include <cuda_fp16.h>
#include <math.h>
#include <stdint.h>

#define BB 4
#define SS 1024
#define DD 1024
#define HH 16
#define DK 64
#define DFF 4096
#define PL (BB * SS * DD)      // plane stride
#define WPL (DD * DD)

// ---------------- scratch (device globals; no allocations allowed) ----------
__device__ __half g_xcat[3 * BB * SS * DD]; // fp16 xq/xk/xv; plane0 reused as sub1_h
__device__ float  g_qkv[3 * BB * SS * DD];  // q/k/v fp32 (tf32-rounded); planes 0/1
                                            // reused as mha_out / ffn2_out after flash
__device__ __half g_wqkvT[3 * DD * DD];     // qkv weightsT [n][d] fp16
__device__ float  g_bqkv[3 * DD];
__device__ __half g_w0T[DD * DD];
__device__ __half g_ff1T[(long long)DFF * DD];
__device__ __half g_ff2T[(long long)DD * DFF];
__device__ float  g_k[BB * SS * DD];        // sub1 (exact fp32)
__device__ float  g_att_raw[(long long)BB * SS * SS];
__device__ __half g_concat[BB * SS * DD];   // flash O (fp16, feeds w0 GEMM)
__device__ __half g_ffn1[(long long)BB * SS * DFF];

// ---------------- helpers ----------------------------------------------------
__device__ __forceinline__ void cp16(void* smem_dst, const void* gmem_src) {
    uint32_t s = (uint32_t)__cvta_generic_to_shared(smem_dst);
    asm volatile("cp.async.ca.shared.global [%0], [%1], 16;" :: "r"(s), "l"(gmem_src));
}
__device__ __forceinline__ void cp_commit() {
    asm volatile("cp.async.commit_group;");
}
template <int N>
__device__ __forceinline__ void cp_wait() {
    asm volatile("cp.async.wait_group %0;" :: "n"(N));
}
__device__ __forceinline__ float rna(float x) {
    uint32_t u;
    asm("cvt.rna.tf32.f32 %0, %1;" : "=r"(u) : "f"(x));
    return __uint_as_float(u);
}
// tf32 mma (flash attention)
__device__ __forceinline__ void mma8(float* d, const uint32_t* a, const uint32_t* b) {
    asm volatile(
        "mma.sync.aligned.m16n8k8.row.col.f32.tf32.tf32.f32 "
        "{%0,%1,%2,%3}, {%4,%5,%6,%7}, {%8,%9}, {%0,%1,%2,%3};"
        : "+f"(d[0]), "+f"(d[1]), "+f"(d[2]), "+f"(d[3])
        : "r"(a[0]), "r"(a[1]), "r"(a[2]), "r"(a[3]), "r"(b[0]), "r"(b[1]));
}
// fp16 mma k16 (GEMMs)
__device__ __forceinline__ void mma16h(float* d, const uint32_t* a, const uint32_t* b) {
    asm volatile(
        "mma.sync.aligned.m16n8k16.row.col.f32.f16.f16.f32 "
        "{%0,%1,%2,%3}, {%4,%5,%6,%7}, {%8,%9}, {%0,%1,%2,%3};"
        : "+f"(d[0]), "+f"(d[1]), "+f"(d[2]), "+f"(d[3])
        : "r"(a[0]), "r"(a[1]), "r"(a[2]), "r"(a[3]), "r"(b[0]), "r"(b[1]));
}
__device__ __forceinline__ uint32_t s2u(const void* p) {
    return (uint32_t)__cvta_generic_to_shared(p);
}
#define LDSM4(r0, r1, r2, r3, addr) \
    asm volatile("ldmatrix.sync.aligned.m8n8.x4.shared.b16 {%0,%1,%2,%3}, [%4];" \
                 : "=r"(r0), "=r"(r1), "=r"(r2), "=r"(r3) : "r"(addr))

// ---------------- prep kernels -----------------------------------------------
__global__ void half_copy(const float* __restrict__ src, __half* __restrict__ dst) {
    int i = blockIdx.x * 256 + threadIdx.x;
    float4 v = ((const float4*)src)[i];
    ((__half2*)dst)[2 * i]     = __floats2half2_rn(v.x, v.y);
    ((__half2*)dst)[2 * i + 1] = __floats2half2_rn(v.z, v.w);
}

__global__ void concat_bias(const float* __restrict__ bq, const float* __restrict__ bk,
                            const float* __restrict__ bv, float* __restrict__ dst) {
    int i = blockIdx.x * 256 + threadIdx.x;
    dst[i] = i < 1024 ? bq[i] : (i < 2048 ? bk[i - 1024] : bv[i - 2048]);
}

// batched transpose + fp16 round: src [z][R][C] fp32 -> dst [z][C][R] fp16
__global__ void transT_h(const float* __restrict__ src, __half* __restrict__ dst,
                         int R, int C) {
    __shared__ float t[32][33];
    long long zo = (long long)blockIdx.z * R * C;
    src += zo; dst += zo;
    int c0 = blockIdx.x * 32, r0 = blockIdx.y * 32;
    int x = threadIdx.x, y = threadIdx.y;   // 32 x 8
    #pragma unroll
    for (int i = 0; i < 32; i += 8)
        t[y + i][x] = src[(long long)(r0 + y + i) * C + c0 + x];
    __syncthreads();
    #pragma unroll
    for (int i = 0; i < 32; i += 8)
        dst[(long long)(c0 + y + i) * R + r0 + x] = __float2half_rn(t[x][y + i]);
}

// ---------------- fp16 GEMM: block 128x128, BK=64 halves, ldmatrix ----------
// A [M][K] fp16 row-major, Bt [N][K] fp16 row-major. 8 warps (2x4),
// warp tile 64x32, 2-stage cp.async. OUT: 0=f32, 1=f32 tf32-rounded, 2=f16.
template <int RELU, int OUT>
__global__ __launch_bounds__(256, 2) void gemm_hm(
    const __half* __restrict__ A, const __half* __restrict__ Bt,
    const float* __restrict__ bias, void* __restrict__ Cv,
    int K, int ldc,
    long long sA, long long sB, long long sBias, long long sC) {
    constexpr int BM = 128, BN = 128, BK = 64;      // BK in halves
    constexpr int ST = 72;                           // halves per row (144 B)
    constexpr int STG = (BM + BN) * ST;              // halves per stage

    extern __shared__ __half smh[];

    const int z = blockIdx.z;
    A += (long long)z * sA;
    Bt += (long long)z * sB;
    if (bias) bias += (long long)z * sBias;

    const int tid = threadIdx.x;
    const int lane = tid & 31, warp = tid >> 5;
    const int wrow = warp >> 2, wcol = warp & 3;
    const int row0 = blockIdx.y * BM, col0 = blockIdx.x * BN;
    const int nk = K / BK;

    auto issue = [&](int kt) {
        __half* as = smh + (kt & 1) * STG;
        __half* bs = as + BM * ST;
        #pragma unroll
        for (int i = 0; i < 4; i++) {
            int id = tid + 256 * i;
            int m = id >> 3, c16 = id & 7;
            cp16(as + m * ST + c16 * 8, A + (long long)(row0 + m) * K + kt * BK + c16 * 8);
        }
        #pragma unroll
        for (int i = 0; i < 4; i++) {
            int id = tid + 256 * i;
            int n = id >> 3, c16 = id & 7;
            cp16(bs + n * ST + c16 * 8, Bt + (long long)(col0 + n) * K + kt * BK + c16 * 8);
        }
        cp_commit();
    };

    float acc[4][4][4] = {};

    issue(0);
    if (nk > 1) issue(1);

    const uint32_t smu = s2u(smh);
    // A x4: lanes 0-15 -> rows m0-15 @k0; 16-31 -> rows @ +16B
    const uint32_t aoff = (wrow * 64 + (lane & 15)) * 144 + (lane >> 4) * 16;
    // B x4: tiles {nt0 k0, nt0 k8, nt1 k0, nt1 k8}
    const uint32_t boff = BM * 144 +
        (wcol * 32 + (lane >> 4) * 8 + (lane & 7)) * 144 + ((lane >> 3) & 1) * 16;

    for (int kt = 0; kt < nk; kt++) {
        if (kt == nk - 1) cp_wait<0>(); else cp_wait<1>();
        __syncthreads();

        const uint32_t stg = smu + (kt & 1) * STG * 2;
        #pragma unroll
        for (int ks = 0; ks < 4; ks++) {               // k16 per step
            const uint32_t k0b = ks * 32;              // 16 halves = 32 B
            uint32_t af[4][4], bq4[2][4];
            #pragma unroll
            for (int mt = 0; mt < 4; mt++)
                LDSM4(af[mt][0], af[mt][1], af[mt][2], af[mt][3],
                      stg + aoff + mt * (16 * 144) + k0b);
            #pragma unroll
            for (int np = 0; np < 2; np++)
                LDSM4(bq4[np][0], bq4[np][1], bq4[np][2], bq4[np][3],
                      stg + boff + np * (16 * 144) + k0b);
            #pragma unroll
            for (int mt = 0; mt < 4; mt++)
                #pragma unroll
                for (int nt = 0; nt < 4; nt++)
                    mma16h(acc[mt][nt], af[mt], &bq4[nt >> 1][(nt & 1) * 2]);
        }
        __syncthreads();
        if (kt + 2 < nk) issue(kt + 2);
    }

    const int r = lane >> 2, c2 = (lane & 3) * 2;
    #pragma unroll
    for (int mt = 0; mt < 4; mt++) {
        int mrow = row0 + wrow * 64 + mt * 16 + r;
        #pragma unroll
        for (int nt = 0; nt < 4; nt++) {
            int ncol = col0 + wcol * 32 + nt * 8 + c2;
            float b0 = 0.0f, b1 = 0.0f;
            if (bias) { b0 = bias[ncol]; b1 = bias[ncol + 1]; }
            float v0 = acc[mt][nt][0] + b0;
            float v1 = acc[mt][nt][1] + b1;
            float v2 = acc[mt][nt][2] + b0;
            float v3 = acc[mt][nt][3] + b1;
            if (RELU) {
                v0 = fmaxf(v0, 0.0f); v1 = fmaxf(v1, 0.0f);
                v2 = fmaxf(v2, 0.0f); v3 = fmaxf(v3, 0.0f);
            }
            if (OUT == 2) {
                __half* Ch = (__half*)Cv + (long long)z * sC;
                *(__half2*)(Ch + (long long)mrow * ldc + ncol) = __floats2half2_rn(v0, v1);
                *(__half2*)(Ch + (long long)(mrow + 8) * ldc + ncol) = __floats2half2_rn(v2, v3);
            } else {
                if (OUT == 1) { v0 = rna(v0); v1 = rna(v1); v2 = rna(v2); v3 = rna(v3); }
                float* Cf = (float*)Cv + (long long)z * sC;
                *(float2*)(Cf + (long long)mrow * ldc + ncol) = make_float2(v0, v1);
                *(float2*)(Cf + (long long)(mrow + 8) * ldc + ncol) = make_float2(v2, v3);
            }
        }
    }
}

// ---------------- fused flash attention (tf32, fp16 concat output) ----------
__global__ __launch_bounds__(256, 1) void flash_attn(
    const float* __restrict__ QKV, const float* __restrict__ mask,
    __half* __restrict__ Oc, float* __restrict__ raw15) {
    constexpr int QST = 68, KST = 68, VST = 72, PST = 68;
    extern __shared__ float sm[];
    float* Qs   = sm;
    float* Ksb  = Qs + 128 * QST;
    float* Vsb  = Ksb + 2 * 64 * KST;
    float* Ps   = Vsb + 2 * 64 * VST;
    float* Msk  = Ps + 128 * PST;
    float* red0 = Msk + 1024;
    float* red1 = red0 + 512;

    const int qb = blockIdx.x, bh = blockIdx.y;
    const int b = bh >> 4, h = bh & 15;
    const float* qp = QKV + ((long long)(b * SS + qb * 128)) * DD + h * 64;
    const float* kp = QKV + PL + ((long long)b * SS) * DD + h * 64;
    const float* vp = QKV + 2 * PL + ((long long)b * SS) * DD + h * 64;
    const float* mp = mask + b * SS;

    const int tid = threadIdx.x, lane = tid & 31, warp = tid >> 5;
    const int wrow = warp >> 2, wcol = warp & 3;
    const int r = lane >> 2, c = lane & 3;

    cp16(Msk + tid * 4, mp + tid * 4);
    #pragma unroll
    for (int i = 0; i < 8; i++) {
        int idx = tid + 256 * i;
        int m = idx >> 4, c4 = (idx & 15) * 4;
        cp16(Qs + m * QST + c4, qp + (long long)m * DD + c4);
    }
    #pragma unroll
    for (int i = 0; i < 4; i++) {
        int idx = tid + 256 * i;
        int n = idx >> 4, c4 = (idx & 15) * 4;
        cp16(Ksb + n * KST + c4, kp + (long long)n * DD + c4);
        cp16(Vsb + n * VST + c4, vp + (long long)n * DD + c4);
    }
    cp_commit();

    const uint32_t qs_u = s2u(Qs), ks0_u = s2u(Ksb), ps_u = s2u(Ps);
    const uint32_t aoffQ = ((wrow * 64 + (lane & 7) + ((lane >> 3) & 1) * 8) * QST
                           + (lane >> 4) * 4) * 4;
    const uint32_t boffK = ((wcol * 16 + (lane & 7) + (lane >> 4) * 8) * KST) * 4
                           + ((lane >> 3) & 1) * 16;
    const uint32_t aoffP = ((wrow * 64 + (lane & 7) + ((lane >> 3) & 1) * 8) * PST
                           + (lane >> 4) * 4) * 4;

    float acc_o[4][2][4] = {};
    float mprev[4][2], lsum[4][2];
    #pragma unroll
    for (int mt = 0; mt < 4; mt++)
        #pragma unroll
        for (int hf = 0; hf < 2; hf++) { mprev[mt][hf] = -1e30f; lsum[mt][hf] = 0.0f; }

    for (int j = 0; j < 16; j++) {
        cp_wait<0>();
        __syncthreads();
        const uint32_t ks_u = ks0_u + (j & 1) * 64 * KST * 4;
        const float* vs = Vsb + (j & 1) * 64 * VST;

        float sv[4][2][4] = {};
        #pragma unroll
        for (int k0 = 0; k0 < 64; k0 += 8) {
            uint32_t af[4][4], bf[2][2];
            #pragma unroll
            for (int mt = 0; mt < 4; mt++)
                LDSM4(af[mt][0], af[mt][1], af[mt][2], af[mt][3],
                      qs_u + aoffQ + mt * (16 * QST * 4) + k0 * 4);
            LDSM4(bf[0][0], bf[0][1], bf[1][0], bf[1][1],
                  ks_u + boffK + k0 * 4);
            #pragma unroll
            for (int mt = 0; mt < 4; mt++)
                #pragma unroll
                for (int nt = 0; nt < 2; nt++)
                    mma8(sv[mt][nt], af[mt], bf[nt]);
        }

        float mk[2][2];
        #pragma unroll
        for (int nt = 0; nt < 2; nt++)
            #pragma unroll
            for (int j2 = 0; j2 < 2; j2++)
                mk[nt][j2] = Msk[j * 64 + wcol * 16 + nt * 8 + 2 * c + j2] * (-1e9f);
        #pragma unroll
        for (int mt = 0; mt < 4; mt++)
            #pragma unroll
            for (int nt = 0; nt < 2; nt++)
                #pragma unroll
                for (int i = 0; i < 4; i++)
                    sv[mt][nt][i] = sv[mt][nt][i] * 0.125f + mk[nt][i & 1];

        if (h == HH - 1) {
            #pragma unroll
            for (int mt = 0; mt < 4; mt++)
                #pragma unroll
                for (int hf = 0; hf < 2; hf++) {
                    int grow = b * SS + qb * 128 + wrow * 64 + mt * 16 + r + 8 * hf;
                    #pragma unroll
                    for (int nt = 0; nt < 2; nt++) {
                        int col = j * 64 + wcol * 16 + nt * 8 + 2 * c;
                        *(float2*)(raw15 + (long long)grow * SS + col) =
                            make_float2(sv[mt][nt][2 * hf], sv[mt][nt][2 * hf + 1]);
                    }
                }
        }

        float mnew[4][2];
        #pragma unroll
        for (int mt = 0; mt < 4; mt++)
            #pragma unroll
            for (int hf = 0; hf < 2; hf++) {
                float v = fmaxf(fmaxf(sv[mt][0][2 * hf], sv[mt][0][2 * hf + 1]),
                                fmaxf(sv[mt][1][2 * hf], sv[mt][1][2 * hf + 1]));
                v = fmaxf(v, __shfl_xor_sync(0xffffffffu, v, 1));
                v = fmaxf(v, __shfl_xor_sync(0xffffffffu, v, 2));
                if (c == 0)
                    red0[(wrow * 64 + mt * 16 + r + 8 * hf) * 4 + wcol] = v;
            }
        __syncthreads();
        #pragma unroll
        for (int mt = 0; mt < 4; mt++)
            #pragma unroll
            for (int hf = 0; hf < 2; hf++) {
                int row = wrow * 64 + mt * 16 + r + 8 * hf;
                float mc = fmaxf(fmaxf(red0[row * 4 + 0], red0[row * 4 + 1]),
                                 fmaxf(red0[row * 4 + 2], red0[row * 4 + 3]));
                mnew[mt][hf] = fmaxf(mprev[mt][hf], mc);
            }

        if (j + 1 < 16) {
            float* kd = Ksb + ((j + 1) & 1) * 64 * KST;
            float* vd = Vsb + ((j + 1) & 1) * 64 * VST;
            #pragma unroll
            for (int i = 0; i < 4; i++) {
                int idx = tid + 256 * i;
                int n = idx >> 4, c4 = (idx & 15) * 4;
                cp16(kd + n * KST + c4, kp + (long long)((j + 1) * 64 + n) * DD + c4);
                cp16(vd + n * VST + c4, vp + (long long)((j + 1) * 64 + n) * DD + c4);
            }
            cp_commit();
        }

        float psum[4][2] = {};
        #pragma unroll
        for (int mt = 0; mt < 4; mt++)
            #pragma unroll
            for (int nt = 0; nt < 2; nt++)
                #pragma unroll
                for (int i = 0; i < 4; i++) {
                    float p = __expf(sv[mt][nt][i] - mnew[mt][i >> 1]);
                    sv[mt][nt][i] = p;
                    psum[mt][i >> 1] += p;
                }
        #pragma unroll
        for (int mt = 0; mt < 4; mt++)
            #pragma unroll
            for (int hf = 0; hf < 2; hf++) {
                float v = psum[mt][hf];
                v += __shfl_xor_sync(0xffffffffu, v, 1);
                v += __shfl_xor_sync(0xffffffffu, v, 2);
                if (c == 0)
                    red1[(wrow * 64 + mt * 16 + r + 8 * hf) * 4 + wcol] = v;
            }
        #pragma unroll
        for (int mt = 0; mt < 4; mt++)
            #pragma unroll
            for (int hf = 0; hf < 2; hf++) {
                int row = wrow * 64 + mt * 16 + r + 8 * hf;
                #pragma unroll
                for (int nt = 0; nt < 2; nt++) {
                    int col = wcol * 16 + nt * 8 + 2 * c;
                    *(float2*)&Ps[row * PST + col] =
                        make_float2(rna(sv[mt][nt][2 * hf]), rna(sv[mt][nt][2 * hf + 1]));
                }
            }
        __syncthreads();

        #pragma unroll
        for (int mt = 0; mt < 4; mt++)
            #pragma unroll
            for (int hf = 0; hf < 2; hf++) {
                int row = wrow * 64 + mt * 16 + r + 8 * hf;
                float sumb = red1[row * 4 + 0] + red1[row * 4 + 1] +
                             red1[row * 4 + 2] + red1[row * 4 + 3];
                float alpha = __expf(mprev[mt][hf] - mnew[mt][hf]);
                lsum[mt][hf] = lsum[mt][hf] * alpha + sumb;
                mprev[mt][hf] = mnew[mt][hf];
                #pragma unroll
                for (int nt = 0; nt < 2; nt++) {
                    acc_o[mt][nt][2 * hf] *= alpha;
                    acc_o[mt][nt][2 * hf + 1] *= alpha;
                }
            }

        #pragma unroll
        for (int k0 = 0; k0 < 64; k0 += 8) {
            uint32_t af[4][4], bf[2][2];
            #pragma unroll
            for (int mt = 0; mt < 4; mt++)
                LDSM4(af[mt][0], af[mt][1], af[mt][2], af[mt][3],
                      ps_u + aoffP + mt * (16 * PST * 4) + k0 * 4);
            #pragma unroll
            for (int nt = 0; nt < 2; nt++) {
                int n = wcol * 16 + nt * 8 + r;
                bf[nt][0] = *(const uint32_t*)&vs[(k0 + c) * VST + n];
                bf[nt][1] = *(const uint32_t*)&vs[(k0 + c + 4) * VST + n];
            }
            #pragma unroll
            for (int mt = 0; mt < 4; mt++)
                #pragma unroll
                for (int nt = 0; nt < 2; nt++)
                    mma8(acc_o[mt][nt], af[mt], bf[nt]);
        }
    }

    #pragma unroll
    for (int mt = 0; mt < 4; mt++) {
        #pragma unroll
        for (int hf = 0; hf < 2; hf++) {
            float inv = 1.0f / lsum[mt][hf];
            int grow = b * SS + qb * 128 + wrow * 64 + mt * 16 + r + 8 * hf;
            #pragma unroll
            for (int nt = 0; nt < 2; nt++) {
                int col = h * 64 + wcol * 16 + nt * 8 + 2 * c;
                *(__half2*)(Oc + (long long)grow * DD + col) =
                    __floats2half2_rn(acc_o[mt][nt][2 * hf] * inv,
                                      acc_o[mt][nt][2 * hf + 1] * inv);
            }
        }
    }
}

// ---------------- softmax of dumped last-head scores -> out_attn -----------
__global__ __launch_bounds__(256) void softmax_out(
    const float* __restrict__ raw, float* __restrict__ out_attn) {
    long long rr = blockIdx.x;
    const float* row = raw + rr * SS;
    float* orow = out_attn + rr * SS;
    int tid = threadIdx.x;

    float vals[4];
    float mx = -1e30f;
    #pragma unroll
    for (int i = 0; i < 4; i++) {
        float v = row[tid + 256 * i];
        vals[i] = v;
        mx = fmaxf(mx, v);
    }
    __shared__ float red[256];
    red[tid] = mx;
    __syncthreads();
    for (int off = 128; off > 0; off >>= 1) {
        if (tid < off) red[tid] = fmaxf(red[tid], red[tid + off]);
        __syncthreads();
    }
    mx = red[0];
    __syncthreads();
    float sum = 0.0f;
    #pragma unroll
    for (int i = 0; i < 4; i++) {
        vals[i] = __expf(vals[i] - mx);
        sum += vals[i];
    }
    red[tid] = sum;
    __syncthreads();
    for (int off = 128; off > 0; off >>= 1) {
        if (tid < off) red[tid] += red[tid + off];
        __syncthreads();
    }
    float inv = 1.0f / red[0];
    #pragma unroll
    for (int i = 0; i < 4; i++)
        orow[tid + 256 * i] = vals[i] * inv;
}

// ---------------- residual add + layernorm (optional fp16 copy) -------------
__global__ __launch_bounds__(256) void add_ln_kernel(
    const float* __restrict__ xa, const float* __restrict__ xb,
    const float* __restrict__ g, const float* __restrict__ bt,
    float* __restrict__ out, __half* __restrict__ out_h) {
    long long rr = blockIdx.x;
    const float* pa = xa + rr * DD;
    const float* pb = xb + rr * DD;
    float* po = out + rr * DD;
    int tid = threadIdx.x;

    float v[4];
    float sum = 0.0f, sq = 0.0f;
    #pragma unroll
    for (int i = 0; i < 4; i++) {
        int cc = tid + 256 * i;
        float x = pa[cc] + pb[cc];
        v[i] = x;
        sum += x;
        sq += x * x;
    }
    __shared__ float r1[256], r2[256];
    r1[tid] = sum;
    r2[tid] = sq;
    __syncthreads();
    for (int off = 128; off > 0; off >>= 1) {
        if (tid < off) { r1[tid] += r1[tid + off]; r2[tid] += r2[tid + off]; }
        __syncthreads();
    }
    float mu = r1[0] * (1.0f / DD);
    float var = r2[0] * (1.0f / DD) - mu * mu;
    float rstd = rsqrtf(var + 1e-6f);

    #pragma unroll
    for (int i = 0; i < 4; i++) {
        int cc = tid + 256 * i;
        float y = (v[i] - mu) * rstd * g[cc] + bt[cc];
        po[cc] = y;
        if (out_h) out_h[rr * DD + cc] = __float2half_rn(y);
    }
}

// ---------------- launch ----------------------------------------------------
static int g_attr_set = 0;

extern "C" void kernel_launch(void* const* d_in, const int* in_sizes, int n_in,
                              void* d_out, int out_size) {
    const float* x_v   = (const float*)d_in[0];
    const float* x_k   = (const float*)d_in[1];
    const float* x_q   = (const float*)d_in[2];
    const float* mask  = (const float*)d_in[3];
    const float* wq    = (const float*)d_in[4];
    const float* bq    = (const float*)d_in[5];
    const float* wk    = (const float*)d_in[6];
    const float* bk    = (const float*)d_in[7];
    const float* wv    = (const float*)d_in[8];
    const float* bv    = (const float*)d_in[9];
    const float* w0    = (const float*)d_in[10];
    const float* b0    = (const float*)d_in[11];
    const float* ln1_g = (const float*)d_in[12];
    const float* ln1_b = (const float*)d_in[13];
    const float* ff1_w = (const float*)d_in[14];
    const float* ff1_b = (const float*)d_in[15];
    const float* ff2_w = (const float*)d_in[16];
    const float* ff2_b = (const float*)d_in[17];
    const float* ln2_g = (const float*)d_in[18];
    const float* ln2_b = (const float*)d_in[19];

    float* out = (float*)d_out;
    float* out_attn = out + (long long)BB * SS * DD;

    const int SM_G = 2 * (256 * 72) * 2;               // 73728 B (halves)
    const int SM_FL = (128 * 68 + 2 * 64 * 68 + 2 * 64 * 72 + 128 * 68
                       + 1024 + 512 + 512) * 4;        // 149504

    if (!g_attr_set) {
        cudaFuncSetAttribute(gemm_hm<0, 0>,
                             cudaFuncAttributeMaxDynamicSharedMemorySize, SM_G);
        cudaFuncSetAttribute(gemm_hm<0, 1>,
                             cudaFuncAttributeMaxDynamicSharedMemorySize, SM_G);
        cudaFuncSetAttribute(gemm_hm<1, 2>,
                             cudaFuncAttributeMaxDynamicSharedMemorySize, SM_G);
        cudaFuncSetAttribute(flash_attn,
                             cudaFuncAttributeMaxDynamicSharedMemorySize, SM_FL);
        g_attr_set = 1;
    }

    __half *pxcat, *pwT, *pw0T, *pff1T, *pff2T, *pconcat, *pffn1;
    float *pqkv, *pbqkv, *pk, *praw;
    cudaGetSymbolAddress((void**)&pxcat, g_xcat);
    cudaGetSymbolAddress((void**)&pqkv, g_qkv);
    cudaGetSymbolAddress((void**)&pwT, g_wqkvT);
    cudaGetSymbolAddress((void**)&pbqkv, g_bqkv);
    cudaGetSymbolAddress((void**)&pw0T, g_w0T);
    cudaGetSymbolAddress((void**)&pff1T, g_ff1T);
    cudaGetSymbolAddress((void**)&pff2T, g_ff2T);
    cudaGetSymbolAddress((void**)&pk, g_k);
    cudaGetSymbolAddress((void**)&praw, g_att_raw);
    cudaGetSymbolAddress((void**)&pconcat, g_concat);
    cudaGetSymbolAddress((void**)&pffn1, g_ffn1);

    dim3 blk(256);
    dim3 tblk(32, 8);
    const int MT = BB * SS;

    // prep: fp16 inputs + transposed fp16 weights + concat bias
    half_copy<<<PL / 1024, blk>>>(x_q, pxcat);
    half_copy<<<PL / 1024, blk>>>(x_k, pxcat + PL);
    half_copy<<<PL / 1024, blk>>>(x_v, pxcat + 2 * PL);
    transT_h<<<dim3(2, 32, HH), tblk>>>(wq, pwT, DD, DK);
    transT_h<<<dim3(2, 32, HH), tblk>>>(wk, pwT + WPL, DD, DK);
    transT_h<<<dim3(2, 32, HH), tblk>>>(wv, pwT + 2 * WPL, DD, DK);
    transT_h<<<dim3(32, 32, 1), tblk>>>(w0, pw0T, DD, DD);
    transT_h<<<dim3(128, 32, 1), tblk>>>(ff1_w, pff1T, DD, DFF);
    transT_h<<<dim3(32, 128, 1), tblk>>>(ff2_w, pff2T, DFF, DD);
    concat_bias<<<12, blk>>>(bq, bk, bv, pbqkv);

    // q/k/v projections: fp16 GEMM, z-batched, tf32-rounded fp32 out
    gemm_hm<0, 1><<<dim3(8, 32, 3), blk, SM_G>>>(pxcat, pwT, pbqkv, pqkv,
        DD, DD, PL, WPL, DD, PL);

    // fused attention (tf32); concat out as fp16; raw last-head scores
    flash_attn<<<dim3(SS / 128, BB * HH), blk, SM_FL>>>(pqkv, mask, pconcat, praw);
    softmax_out<<<BB * SS, blk>>>(praw, out_attn);

    // mha_out = concat @ w0 + b0  -> g_qkv plane 0 (fp32, free after flash)
    gemm_hm<0, 0><<<dim3(8, 32, 1), blk, SM_G>>>(pconcat, pw0T, b0, pqkv,
        DD, DD, 0, 0, 0, 0);

    // sub1 = LN1(x_q + mha_out): exact -> g_k, fp16 -> xcat plane 0
    add_ln_kernel<<<MT, blk>>>(x_q, pqkv, ln1_g, ln1_b, pk, pxcat);

    // ffn1 = relu(sub1 @ ff1_w + ff1_b) -> fp16
    gemm_hm<1, 2><<<dim3(32, 32, 1), blk, SM_G>>>(pxcat, pff1T, ff1_b, pffn1,
        DD, DFF, 0, 0, 0, 0);

    // ffn2 = ffn1 @ ff2_w + ff2_b -> g_qkv plane 1 (fp32)
    gemm_hm<0, 0><<<dim3(8, 32, 1), blk, SM_G>>>(pffn1, pff2T, ff2_b, pqkv + PL,
        DFF, DD, 0, 0, 0, 0);

    // out = LN2(sub1 + ffn2) -> d_out first half
    add_ln_kernel<<<MT, blk>>>(pk, pqkv + PL, ln2_g, ln2_b, out, nullptr);
}

// round 17
// speedup vs baseline: 2.1213x; 1.1343x over previous
#include <cuda_runtime.h>
#include <cuda_fp16.h>
#include <math.h>
#include <stdint.h>

#define BB 4
#define SS 1024
#define DD 1024
#define HH 16
#define DK 64
#define DFF 4096
#define PL (BB * SS * DD)      // plane stride
#define WPL (DD * DD)

// ---------------- scratch (device globals; no allocations allowed) ----------
__device__ __half g_xcat[3 * BB * SS * DD]; // fp16 xq/xk/xv; plane0 reused as sub1_h
__device__ __half g_qkv[3 * BB * SS * DD];  // q/k/v fp16 planes
__device__ __half g_wqkvT[3 * DD * DD];     // qkv weightsT [n][d] fp16
__device__ float  g_bqkv[3 * DD];
__device__ __half g_w0T[DD * DD];
__device__ __half g_ff1T[(long long)DFF * DD];
__device__ __half g_ff2T[(long long)DD * DFF];
__device__ float  g_k[BB * SS * DD];        // sub1 (exact fp32)
__device__ float  g_att_raw[(long long)BB * SS * SS]; // raw scores (16MB);
                                            // reused as mha_out AFTER softmax_out
__device__ float  g_ffn2[BB * SS * DD];     // dedicated ffn2 fp32 scratch
__device__ __half g_concat[BB * SS * DD];   // flash O (fp16, feeds w0 GEMM)
__device__ __half g_ffn1[(long long)BB * SS * DFF];

// ---------------- helpers ----------------------------------------------------
__device__ __forceinline__ void cp16(void* smem_dst, const void* gmem_src) {
    uint32_t s = (uint32_t)__cvta_generic_to_shared(smem_dst);
    asm volatile("cp.async.ca.shared.global [%0], [%1], 16;" :: "r"(s), "l"(gmem_src));
}
__device__ __forceinline__ void cp_commit() {
    asm volatile("cp.async.commit_group;");
}
template <int N>
__device__ __forceinline__ void cp_wait() {
    asm volatile("cp.async.wait_group %0;" :: "n"(N));
}
// fp16 mma k16
__device__ __forceinline__ void mma16h(float* d, const uint32_t* a, const uint32_t* b) {
    asm volatile(
        "mma.sync.aligned.m16n8k16.row.col.f32.f16.f16.f32 "
        "{%0,%1,%2,%3}, {%4,%5,%6,%7}, {%8,%9}, {%0,%1,%2,%3};"
        : "+f"(d[0]), "+f"(d[1]), "+f"(d[2]), "+f"(d[3])
        : "r"(a[0]), "r"(a[1]), "r"(a[2]), "r"(a[3]), "r"(b[0]), "r"(b[1]));
}
__device__ __forceinline__ uint32_t s2u(const void* p) {
    return (uint32_t)__cvta_generic_to_shared(p);
}
#define LDSM4(r0, r1, r2, r3, addr) \
    asm volatile("ldmatrix.sync.aligned.m8n8.x4.shared.b16 {%0,%1,%2,%3}, [%4];" \
                 : "=r"(r0), "=r"(r1), "=r"(r2), "=r"(r3) : "r"(addr))
#define MOVM(d, s) \
    asm volatile("movmatrix.sync.aligned.m8n8.trans.b16 %0, %1;" : "=r"(d) : "r"(s))

// ---------------- prep kernels -----------------------------------------------
__global__ void half_copy(const float* __restrict__ src, __half* __restrict__ dst) {
    int i = blockIdx.x * 256 + threadIdx.x;
    float4 v = ((const float4*)src)[i];
    ((__half2*)dst)[2 * i]     = __floats2half2_rn(v.x, v.y);
    ((__half2*)dst)[2 * i + 1] = __floats2half2_rn(v.z, v.w);
}

__global__ void concat_bias(const float* __restrict__ bq, const float* __restrict__ bk,
                            const float* __restrict__ bv, float* __restrict__ dst) {
    int i = blockIdx.x * 256 + threadIdx.x;
    dst[i] = i < 1024 ? bq[i] : (i < 2048 ? bk[i - 1024] : bv[i - 2048]);
}

// batched transpose + fp16 round: src [z][R][C] fp32 -> dst [z][C][R] fp16
__global__ void transT_h(const float* __restrict__ src, __half* __restrict__ dst,
                         int R, int C) {
    __shared__ float t[32][33];
    long long zo = (long long)blockIdx.z * R * C;
    src += zo; dst += zo;
    int c0 = blockIdx.x * 32, r0 = blockIdx.y * 32;
    int x = threadIdx.x, y = threadIdx.y;   // 32 x 8
    #pragma unroll
    for (int i = 0; i < 32; i += 8)
        t[y + i][x] = src[(long long)(r0 + y + i) * C + c0 + x];
    __syncthreads();
    #pragma unroll
    for (int i = 0; i < 32; i += 8)
        dst[(long long)(c0 + y + i) * R + r0 + x] = __float2half_rn(t[x][y + i]);
}

// ---------------- fp16 GEMM: block 128x128, BK=64 halves, ldmatrix ----------
// OUT: 0=f32 out, 2=f16 out.
template <int RELU, int OUT>
__global__ __launch_bounds__(256, 2) void gemm_hm(
    const __half* __restrict__ A, const __half* __restrict__ Bt,
    const float* __restrict__ bias, void* __restrict__ Cv,
    int K, int ldc,
    long long sA, long long sB, long long sBias, long long sC) {
    constexpr int BM = 128, BN = 128, BK = 64;
    constexpr int ST = 72;                           // halves per row (144 B)
    constexpr int STG = (BM + BN) * ST;

    extern __shared__ __half smh[];

    const int z = blockIdx.z;
    A += (long long)z * sA;
    Bt += (long long)z * sB;
    if (bias) bias += (long long)z * sBias;

    const int tid = threadIdx.x;
    const int lane = tid & 31, warp = tid >> 5;
    const int wrow = warp >> 2, wcol = warp & 3;
    const int row0 = blockIdx.y * BM, col0 = blockIdx.x * BN;
    const int nk = K / BK;

    auto issue = [&](int kt) {
        __half* as = smh + (kt & 1) * STG;
        __half* bs = as + BM * ST;
        #pragma unroll
        for (int i = 0; i < 4; i++) {
            int id = tid + 256 * i;
            int m = id >> 3, c16 = id & 7;
            cp16(as + m * ST + c16 * 8, A + (long long)(row0 + m) * K + kt * BK + c16 * 8);
        }
        #pragma unroll
        for (int i = 0; i < 4; i++) {
            int id = tid + 256 * i;
            int n = id >> 3, c16 = id & 7;
            cp16(bs + n * ST + c16 * 8, Bt + (long long)(col0 + n) * K + kt * BK + c16 * 8);
        }
        cp_commit();
    };

    float acc[4][4][4] = {};

    issue(0);
    if (nk > 1) issue(1);

    const uint32_t smu = s2u(smh);
    const uint32_t aoff = (wrow * 64 + (lane & 15)) * 144 + (lane >> 4) * 16;
    const uint32_t boff = BM * 144 +
        (wcol * 32 + (lane >> 4) * 8 + (lane & 7)) * 144 + ((lane >> 3) & 1) * 16;

    for (int kt = 0; kt < nk; kt++) {
        if (kt == nk - 1) cp_wait<0>(); else cp_wait<1>();
        __syncthreads();

        const uint32_t stg = smu + (kt & 1) * STG * 2;
        #pragma unroll
        for (int ks = 0; ks < 4; ks++) {
            const uint32_t k0b = ks * 32;
            uint32_t af[4][4], bq4[2][4];
            #pragma unroll
            for (int mt = 0; mt < 4; mt++)
                LDSM4(af[mt][0], af[mt][1], af[mt][2], af[mt][3],
                      stg + aoff + mt * (16 * 144) + k0b);
            #pragma unroll
            for (int np = 0; np < 2; np++)
                LDSM4(bq4[np][0], bq4[np][1], bq4[np][2], bq4[np][3],
                      stg + boff + np * (16 * 144) + k0b);
            #pragma unroll
            for (int mt = 0; mt < 4; mt++)
                #pragma unroll
                for (int nt = 0; nt < 4; nt++)
                    mma16h(acc[mt][nt], af[mt], &bq4[nt >> 1][(nt & 1) * 2]);
        }
        __syncthreads();
        if (kt + 2 < nk) issue(kt + 2);
    }

    const int r = lane >> 2, c2 = (lane & 3) * 2;
    #pragma unroll
    for (int mt = 0; mt < 4; mt++) {
        int mrow = row0 + wrow * 64 + mt * 16 + r;
        #pragma unroll
        for (int nt = 0; nt < 4; nt++) {
            int ncol = col0 + wcol * 32 + nt * 8 + c2;
            float b0 = 0.0f, b1 = 0.0f;
            if (bias) { b0 = bias[ncol]; b1 = bias[ncol + 1]; }
            float v0 = acc[mt][nt][0] + b0;
            float v1 = acc[mt][nt][1] + b1;
            float v2 = acc[mt][nt][2] + b0;
            float v3 = acc[mt][nt][3] + b1;
            if (RELU) {
                v0 = fmaxf(v0, 0.0f); v1 = fmaxf(v1, 0.0f);
                v2 = fmaxf(v2, 0.0f); v3 = fmaxf(v3, 0.0f);
            }
            if (OUT == 2) {
                __half* Ch = (__half*)Cv + (long long)z * sC;
                *(__half2*)(Ch + (long long)mrow * ldc + ncol) = __floats2half2_rn(v0, v1);
                *(__half2*)(Ch + (long long)(mrow + 8) * ldc + ncol) = __floats2half2_rn(v2, v3);
            } else {
                float* Cf = (float*)Cv + (long long)z * sC;
                *(float2*)(Cf + (long long)mrow * ldc + ncol) = make_float2(v0, v1);
                *(float2*)(Cf + (long long)(mrow + 8) * ldc + ncol) = make_float2(v2, v3);
            }
        }
    }
}

// ---------------- fused flash attention (fp16 mma, 2 CTA/SM) ----------------
// grid (S/128, B*H). QKV fp16 planes: q +0, k +PL, v +2*PL.
// V b-fragments: non-trans ldmatrix (validated mapping) + movmatrix transpose.
__global__ __launch_bounds__(256, 2) void flash_attn(
    const __half* __restrict__ QKV, const float* __restrict__ mask,
    __half* __restrict__ Oc, float* __restrict__ raw15) {
    constexpr int ST = 72;                       // halves per row (144 B)
    constexpr int SMEM_BYTES = 4 * (128 * ST) * 2 + (1024 + 512 + 512) * 4;
    extern __shared__ __half smh[];
    __half* Qs  = smh;                           // 128*72
    __half* Ksb = Qs + 128 * ST;                 // 2*64*72
    __half* Vsb = Ksb + 2 * 64 * ST;             // 2*64*72
    __half* Ps  = Vsb + 2 * 64 * ST;             // 128*72
    float* Msk  = (float*)(Ps + 128 * ST);       // 1024 f
    float* red0 = Msk + 1024;                    // 512 f
    float* red1 = red0 + 512;                    // 512 f

    const int qb = blockIdx.x, bh = blockIdx.y;
    const int b = bh >> 4, h = bh & 15;
    const __half* qp = QKV + ((long long)(b * SS + qb * 128)) * DD + h * 64;
    const __half* kp = QKV + PL + ((long long)b * SS) * DD + h * 64;
    const __half* vp = QKV + 2 * PL + ((long long)b * SS) * DD + h * 64;
    const float* mp = mask + b * SS;

    const int tid = threadIdx.x, lane = tid & 31, warp = tid >> 5;
    const int wrow = warp >> 2, wcol = warp & 3;
    const int r = lane >> 2, c = lane & 3;

    // zero all SMEM first (defensive: unwritten bytes read as 0, never NaN)
    {
        uint4* z4 = (uint4*)smh;
        #pragma unroll
        for (int i = 0; i < SMEM_BYTES / 16 / 256; i++)
            z4[tid + 256 * i] = make_uint4(0u, 0u, 0u, 0u);
    }
    __syncthreads();

    cp16(Msk + tid * 4, mp + tid * 4);
    #pragma unroll
    for (int i = 0; i < 4; i++) {                // Q: 128x64 halves
        int id = tid + 256 * i;
        int m = id >> 3, c8 = (id & 7) * 8;
        cp16(Qs + m * ST + c8, qp + (long long)m * DD + c8);
    }
    #pragma unroll
    for (int i = 0; i < 2; i++) {                // K,V stage 0: 64x64 halves
        int id = tid + 256 * i;
        int n = id >> 3, c8 = (id & 7) * 8;
        cp16(Ksb + n * ST + c8, kp + (long long)n * DD + c8);
        cp16(Vsb + n * ST + c8, vp + (long long)n * DD + c8);
    }
    cp_commit();

    const uint32_t qs_u = s2u(Qs), ks0_u = s2u(Ksb), vs0_u = s2u(Vsb), ps_u = s2u(Ps);
    const uint32_t aoffQ = (wrow * 64 + (lane & 15)) * 144 + (lane >> 4) * 16;
    const uint32_t boffK = (wcol * 16 + (lane >> 4) * 8 + (lane & 7)) * 144
                           + ((lane >> 3) & 1) * 16;
    const uint32_t aoffP = aoffQ;                // same geometry (ST identical)
    // non-trans V addresses: rows = seq(k), col group = dk(n) 8-block
    const uint32_t voffV = ((lane & 7) + ((lane >> 3) & 1) * 8) * 144
                           + (lane >> 4) * 16 + wcol * 32;

    float acc_o[4][2][4] = {};
    float mprev[4][2], lsum[4][2];
    #pragma unroll
    for (int mt = 0; mt < 4; mt++)
        #pragma unroll
        for (int hf = 0; hf < 2; hf++) { mprev[mt][hf] = -1e30f; lsum[mt][hf] = 0.0f; }

    for (int j = 0; j < 16; j++) {
        cp_wait<0>();
        __syncthreads();
        const uint32_t ks_u = ks0_u + (j & 1) * 64 * ST * 2;
        const uint32_t vs_u = vs0_u + (j & 1) * 64 * ST * 2;

        // S = Q @ K^T  (fp16 k16)
        float sv[4][2][4] = {};
        #pragma unroll
        for (int ks = 0; ks < 4; ks++) {
            uint32_t af[4][4], bf4[4];
            #pragma unroll
            for (int mt = 0; mt < 4; mt++)
                LDSM4(af[mt][0], af[mt][1], af[mt][2], af[mt][3],
                      qs_u + aoffQ + mt * (16 * 144) + ks * 32);
            LDSM4(bf4[0], bf4[1], bf4[2], bf4[3], ks_u + boffK + ks * 32);
            #pragma unroll
            for (int mt = 0; mt < 4; mt++)
                #pragma unroll
                for (int nt = 0; nt < 2; nt++)
                    mma16h(sv[mt][nt], af[mt], &bf4[nt * 2]);
        }

        float mk[2][2];
        #pragma unroll
        for (int nt = 0; nt < 2; nt++)
            #pragma unroll
            for (int j2 = 0; j2 < 2; j2++)
                mk[nt][j2] = Msk[j * 64 + wcol * 16 + nt * 8 + 2 * c + j2] * (-1e9f);
        #pragma unroll
        for (int mt = 0; mt < 4; mt++)
            #pragma unroll
            for (int nt = 0; nt < 2; nt++)
                #pragma unroll
                for (int i = 0; i < 4; i++)
                    sv[mt][nt][i] = sv[mt][nt][i] * 0.125f + mk[nt][i & 1];

        if (h == HH - 1) {
            #pragma unroll
            for (int mt = 0; mt < 4; mt++)
                #pragma unroll
                for (int hf = 0; hf < 2; hf++) {
                    int grow = b * SS + qb * 128 + wrow * 64 + mt * 16 + r + 8 * hf;
                    #pragma unroll
                    for (int nt = 0; nt < 2; nt++) {
                        int col = j * 64 + wcol * 16 + nt * 8 + 2 * c;
                        *(float2*)(raw15 + (long long)grow * SS + col) =
                            make_float2(sv[mt][nt][2 * hf], sv[mt][nt][2 * hf + 1]);
                    }
                }
        }

        float mnew[4][2];
        #pragma unroll
        for (int mt = 0; mt < 4; mt++)
            #pragma unroll
            for (int hf = 0; hf < 2; hf++) {
                float v = fmaxf(fmaxf(sv[mt][0][2 * hf], sv[mt][0][2 * hf + 1]),
                                fmaxf(sv[mt][1][2 * hf], sv[mt][1][2 * hf + 1]));
                v = fmaxf(v, __shfl_xor_sync(0xffffffffu, v, 1));
                v = fmaxf(v, __shfl_xor_sync(0xffffffffu, v, 2));
                if (c == 0)
                    red0[(wrow * 64 + mt * 16 + r + 8 * hf) * 4 + wcol] = v;
            }
        __syncthreads();
        #pragma unroll
        for (int mt = 0; mt < 4; mt++)
            #pragma unroll
            for (int hf = 0; hf < 2; hf++) {
                int row = wrow * 64 + mt * 16 + r + 8 * hf;
                float mc = fmaxf(fmaxf(red0[row * 4 + 0], red0[row * 4 + 1]),
                                 fmaxf(red0[row * 4 + 2], red0[row * 4 + 3]));
                mnew[mt][hf] = fmaxf(mprev[mt][hf], mc);
            }

        if (j + 1 < 16) {
            __half* kd = Ksb + ((j + 1) & 1) * 64 * ST;
            __half* vd = Vsb + ((j + 1) & 1) * 64 * ST;
            #pragma unroll
            for (int i = 0; i < 2; i++) {
                int id = tid + 256 * i;
                int n = id >> 3, c8 = (id & 7) * 8;
                cp16(kd + n * ST + c8, kp + (long long)((j + 1) * 64 + n) * DD + c8);
                cp16(vd + n * ST + c8, vp + (long long)((j + 1) * 64 + n) * DD + c8);
            }
            cp_commit();
        }

        float psum[4][2] = {};
        #pragma unroll
        for (int mt = 0; mt < 4; mt++)
            #pragma unroll
            for (int nt = 0; nt < 2; nt++)
                #pragma unroll
                for (int i = 0; i < 4; i++) {
                    float p = __expf(sv[mt][nt][i] - mnew[mt][i >> 1]);
                    sv[mt][nt][i] = p;
                    psum[mt][i >> 1] += p;
                }
        #pragma unroll
        for (int mt = 0; mt < 4; mt++)
            #pragma unroll
            for (int hf = 0; hf < 2; hf++) {
                float v = psum[mt][hf];
                v += __shfl_xor_sync(0xffffffffu, v, 1);
                v += __shfl_xor_sync(0xffffffffu, v, 2);
                if (c == 0)
                    red1[(wrow * 64 + mt * 16 + r + 8 * hf) * 4 + wcol] = v;
            }
        #pragma unroll
        for (int mt = 0; mt < 4; mt++)
            #pragma unroll
            for (int hf = 0; hf < 2; hf++) {
                int row = wrow * 64 + mt * 16 + r + 8 * hf;
                #pragma unroll
                for (int nt = 0; nt < 2; nt++) {
                    int col = wcol * 16 + nt * 8 + 2 * c;
                    *(__half2*)&Ps[row * ST + col] =
                        __floats2half2_rn(sv[mt][nt][2 * hf], sv[mt][nt][2 * hf + 1]);
                }
            }
        __syncthreads();

        #pragma unroll
        for (int mt = 0; mt < 4; mt++)
            #pragma unroll
            for (int hf = 0; hf < 2; hf++) {
                int row = wrow * 64 + mt * 16 + r + 8 * hf;
                float sumb = red1[row * 4 + 0] + red1[row * 4 + 1] +
                             red1[row * 4 + 2] + red1[row * 4 + 3];
                float alpha = __expf(mprev[mt][hf] - mnew[mt][hf]);
                lsum[mt][hf] = lsum[mt][hf] * alpha + sumb;
                mprev[mt][hf] = mnew[mt][hf];
                #pragma unroll
                for (int nt = 0; nt < 2; nt++) {
                    acc_o[mt][nt][2 * hf] *= alpha;
                    acc_o[mt][nt][2 * hf + 1] *= alpha;
                }
            }

        // O += P @ V  (fp16; V: non-trans ldmatrix + movmatrix -> b-fragments)
        #pragma unroll
        for (int ks = 0; ks < 4; ks++) {
            uint32_t af[4][4], va[4], vb[4];
            #pragma unroll
            for (int mt = 0; mt < 4; mt++)
                LDSM4(af[mt][0], af[mt][1], af[mt][2], af[mt][3],
                      ps_u + aoffP + mt * (16 * 144) + ks * 32);
            LDSM4(va[0], va[1], va[2], va[3],
                  vs_u + voffV + ks * (16 * 144));
            MOVM(vb[0], va[0]); MOVM(vb[1], va[1]);
            MOVM(vb[2], va[2]); MOVM(vb[3], va[3]);
            #pragma unroll
            for (int mt = 0; mt < 4; mt++)
                #pragma unroll
                for (int nt = 0; nt < 2; nt++)
                    mma16h(acc_o[mt][nt], af[mt], &vb[nt * 2]);
        }
    }

    #pragma unroll
    for (int mt = 0; mt < 4; mt++) {
        #pragma unroll
        for (int hf = 0; hf < 2; hf++) {
            float inv = 1.0f / lsum[mt][hf];
            int grow = b * SS + qb * 128 + wrow * 64 + mt * 16 + r + 8 * hf;
            #pragma unroll
            for (int nt = 0; nt < 2; nt++) {
                int col = h * 64 + wcol * 16 + nt * 8 + 2 * c;
                *(__half2*)(Oc + (long long)grow * DD + col) =
                    __floats2half2_rn(acc_o[mt][nt][2 * hf] * inv,
                                      acc_o[mt][nt][2 * hf + 1] * inv);
            }
        }
    }
}

// ---------------- softmax of dumped last-head scores -> out_attn -----------
__global__ __launch_bounds__(256) void softmax_out(
    const float* __restrict__ raw, float* __restrict__ out_attn) {
    long long rr = blockIdx.x;
    const float* row = raw + rr * SS;
    float* orow = out_attn + rr * SS;
    int tid = threadIdx.x;

    float vals[4];
    float mx = -1e30f;
    #pragma unroll
    for (int i = 0; i < 4; i++) {
        float v = row[tid + 256 * i];
        vals[i] = v;
        mx = fmaxf(mx, v);
    }
    __shared__ float red[256];
    red[tid] = mx;
    __syncthreads();
    for (int off = 128; off > 0; off >>= 1) {
        if (tid < off) red[tid] = fmaxf(red[tid], red[tid + off]);
        __syncthreads();
    }
    mx = red[0];
    __syncthreads();
    float sum = 0.0f;
    #pragma unroll
    for (int i = 0; i < 4; i++) {
        vals[i] = __expf(vals[i] - mx);
        sum += vals[i];
    }
    red[tid] = sum;
    __syncthreads();
    for (int off = 128; off > 0; off >>= 1) {
        if (tid < off) red[tid] += red[tid + off];
        __syncthreads();
    }
    float inv = 1.0f / red[0];
    #pragma unroll
    for (int i = 0; i < 4; i++)
        orow[tid + 256 * i] = vals[i] * inv;
}

// ---------------- residual add + layernorm (optional fp16 copy) -------------
__global__ __launch_bounds__(256) void add_ln_kernel(
    const float* __restrict__ xa, const float* __restrict__ xb,
    const float* __restrict__ g, const float* __restrict__ bt,
    float* __restrict__ out, __half* __restrict__ out_h) {
    long long rr = blockIdx.x;
    const float* pa = xa + rr * DD;
    const float* pb = xb + rr * DD;
    float* po = out + rr * DD;
    int tid = threadIdx.x;

    float v[4];
    float sum = 0.0f, sq = 0.0f;
    #pragma unroll
    for (int i = 0; i < 4; i++) {
        int cc = tid + 256 * i;
        float x = pa[cc] + pb[cc];
        v[i] = x;
        sum += x;
        sq += x * x;
    }
    __shared__ float r1[256], r2[256];
    r1[tid] = sum;
    r2[tid] = sq;
    __syncthreads();
    for (int off = 128; off > 0; off >>= 1) {
        if (tid < off) { r1[tid] += r1[tid + off]; r2[tid] += r2[tid + off]; }
        __syncthreads();
    }
    float mu = r1[0] * (1.0f / DD);
    float var = r2[0] * (1.0f / DD) - mu * mu;
    float rstd = rsqrtf(var + 1e-6f);

    #pragma unroll
    for (int i = 0; i < 4; i++) {
        int cc = tid + 256 * i;
        float y = (v[i] - mu) * rstd * g[cc] + bt[cc];
        po[cc] = y;
        if (out_h) out_h[rr * DD + cc] = __float2half_rn(y);
    }
}

// ---------------- launch ----------------------------------------------------
static int g_attr_set = 0;

extern "C" void kernel_launch(void* const* d_in, const int* in_sizes, int n_in,
                              void* d_out, int out_size) {
    const float* x_v   = (const float*)d_in[0];
    const float* x_k   = (const float*)d_in[1];
    const float* x_q   = (const float*)d_in[2];
    const float* mask  = (const float*)d_in[3];
    const float* wq    = (const float*)d_in[4];
    const float* bq    = (const float*)d_in[5];
    const float* wk    = (const float*)d_in[6];
    const float* bk    = (const float*)d_in[7];
    const float* wv    = (const float*)d_in[8];
    const float* bv    = (const float*)d_in[9];
    const float* w0    = (const float*)d_in[10];
    const float* b0    = (const float*)d_in[11];
    const float* ln1_g = (const float*)d_in[12];
    const float* ln1_b = (const float*)d_in[13];
    const float* ff1_w = (const float*)d_in[14];
    const float* ff1_b = (const float*)d_in[15];
    const float* ff2_w = (const float*)d_in[16];
    const float* ff2_b = (const float*)d_in[17];
    const float* ln2_g = (const float*)d_in[18];
    const float* ln2_b = (const float*)d_in[19];

    float* out = (float*)d_out;
    float* out_attn = out + (long long)BB * SS * DD;

    const int SM_G = 2 * (256 * 72) * 2;               // 73728
    const int SM_FL = 4 * (128 * 72) * 2 + (1024 + 512 + 512) * 4;  // 81920

    if (!g_attr_set) {
        cudaFuncSetAttribute(gemm_hm<0, 0>,
                             cudaFuncAttributeMaxDynamicSharedMemorySize, SM_G);
        cudaFuncSetAttribute(gemm_hm<0, 2>,
                             cudaFuncAttributeMaxDynamicSharedMemorySize, SM_G);
        cudaFuncSetAttribute(gemm_hm<1, 2>,
                             cudaFuncAttributeMaxDynamicSharedMemorySize, SM_G);
        cudaFuncSetAttribute(flash_attn,
                             cudaFuncAttributeMaxDynamicSharedMemorySize, SM_FL);
        g_attr_set = 1;
    }

    __half *pxcat, *pqkv, *pwT, *pw0T, *pff1T, *pff2T, *pconcat, *pffn1;
    float *pbqkv, *pk, *praw, *pffn2;
    cudaGetSymbolAddress((void**)&pxcat, g_xcat);
    cudaGetSymbolAddress((void**)&pqkv, g_qkv);
    cudaGetSymbolAddress((void**)&pwT, g_wqkvT);
    cudaGetSymbolAddress((void**)&pbqkv, g_bqkv);
    cudaGetSymbolAddress((void**)&pw0T, g_w0T);
    cudaGetSymbolAddress((void**)&pff1T, g_ff1T);
    cudaGetSymbolAddress((void**)&pff2T, g_ff2T);
    cudaGetSymbolAddress((void**)&pk, g_k);
    cudaGetSymbolAddress((void**)&praw, g_att_raw);
    cudaGetSymbolAddress((void**)&pffn2, g_ffn2);
    cudaGetSymbolAddress((void**)&pconcat, g_concat);
    cudaGetSymbolAddress((void**)&pffn1, g_ffn1);

    // mha_out reuses g_att_raw (16MB, free after softmax_out). ffn2 has its
    // OWN buffer — g_att_raw is only PL floats total (the R14 overflow bug).
    float* pmha = praw;

    dim3 blk(256);
    dim3 tblk(32, 8);
    const int MT = BB * SS;

    // prep: fp16 inputs + transposed fp16 weights + concat bias
    half_copy<<<PL / 1024, blk>>>(x_q, pxcat);
    half_copy<<<PL / 1024, blk>>>(x_k, pxcat + PL);
    half_copy<<<PL / 1024, blk>>>(x_v, pxcat + 2 * PL);
    transT_h<<<dim3(2, 32, HH), tblk>>>(wq, pwT, DD, DK);
    transT_h<<<dim3(2, 32, HH), tblk>>>(wk, pwT + WPL, DD, DK);
    transT_h<<<dim3(2, 32, HH), tblk>>>(wv, pwT + 2 * WPL, DD, DK);
    transT_h<<<dim3(32, 32, 1), tblk>>>(w0, pw0T, DD, DD);
    transT_h<<<dim3(128, 32, 1), tblk>>>(ff1_w, pff1T, DD, DFF);
    transT_h<<<dim3(32, 128, 1), tblk>>>(ff2_w, pff2T, DFF, DD);
    concat_bias<<<12, blk>>>(bq, bk, bv, pbqkv);

    // q/k/v projections: fp16 GEMM, z-batched, fp16 out planes
    gemm_hm<0, 2><<<dim3(8, 32, 3), blk, SM_G>>>(pxcat, pwT, pbqkv, pqkv,
        DD, DD, PL, WPL, DD, PL);

    // fused attention (fp16 mma); concat out fp16; raw last-head scores fp32
    flash_attn<<<dim3(SS / 128, BB * HH), blk, SM_FL>>>(pqkv, mask, pconcat, praw);
    softmax_out<<<BB * SS, blk>>>(praw, out_attn);

    // mha_out = concat @ w0 + b0  -> g_att_raw (free after softmax_out)
    gemm_hm<0, 0><<<dim3(8, 32, 1), blk, SM_G>>>(pconcat, pw0T, b0, pmha,
        DD, DD, 0, 0, 0, 0);

    // sub1 = LN1(x_q + mha_out): exact -> g_k, fp16 -> xcat plane 0
    add_ln_kernel<<<MT, blk>>>(x_q, pmha, ln1_g, ln1_b, pk, pxcat);

    // ffn1 = relu(sub1 @ ff1_w + ff1_b) -> fp16
    gemm_hm<1, 2><<<dim3(32, 32, 1), blk, SM_G>>>(pxcat, pff1T, ff1_b, pffn1,
        DD, DFF, 0, 0, 0, 0);

    // ffn2 = ffn1 @ ff2_w + ff2_b -> dedicated fp32 scratch
    gemm_hm<0, 0><<<dim3(8, 32, 1), blk, SM_G>>>(pffn1, pff2T, ff2_b, pffn2,
        DFF, DD, 0, 0, 0, 0);

    // out = LN2(sub1 + ffn2) -> d_out first half
    add_ln_kernel<<<MT, blk>>>(pk, pffn2, ln2_g, ln2_b, out, nullptr);
}